// round 7
// baseline (speedup 1.0000x reference)
#include <cuda_runtime.h>
#include <cuda_fp16.h>

#define DIM 32
#define NODES_MAX 100000
#define EDGES_MAX 3200000
#define CAP 192   // per-node bucket capacity (Poisson(32): P(deg>70) ~ 1e-11)

// ---------------- scratch (device globals; no allocation allowed) ------------
// Invariant at entry to kernel_launch: g_cnt all-zero, g_pool all-zero.
// (zero at load; last k_layer resets g_cnt, k_head resets g_pool every call)
__device__ __half g_p0[NODES_MAX * DIM];
__device__ __half g_p1[NODES_MAX * DIM];
__device__ int    g_cnt[NODES_MAX];
__device__ int    g_bucket[NODES_MAX * CAP];
__device__ float  g_pool[DIM];

// ---------------- one-pass bucket fill (replaces hist+scan+fill) -------------
__global__ void k_fillb(const int* __restrict__ src, const int* __restrict__ dst,
                        int n_edges) {
    int stride = gridDim.x * blockDim.x;
    for (int i = blockIdx.x * blockDim.x + threadIdx.x; i < n_edges; i += stride) {
        int d = __ldg(&dst[i]);
        int pos = atomicAdd(&g_cnt[d], 1);
        if (pos < CAP) g_bucket[d * CAP + pos] = __ldg(&src[i]);
    }
}

// ---------------- input projection: p0 = x @ w1a (half output) ---------------
__global__ void k_proj(const float* __restrict__ x, const float* __restrict__ w1a,
                       int n_nodes, int in_dim) {
    __shared__ float ws[96 * DIM];
    for (int i = threadIdx.x; i < in_dim * DIM; i += blockDim.x) ws[i] = w1a[i];
    __syncthreads();
    int lane = threadIdx.x & 31;
    int warp = (blockIdx.x * blockDim.x + threadIdx.x) >> 5;
    int nwarp = (gridDim.x * blockDim.x) >> 5;
    for (int n = warp; n < n_nodes; n += nwarp) {
        const float* xr = x + (size_t)n * in_dim;
        float xv0 = (lane < in_dim) ? __ldg(&xr[lane]) : 0.0f;
        float xv1 = (32 + lane < in_dim) ? __ldg(&xr[32 + lane]) : 0.0f;
        float xv2 = (64 + lane < in_dim) ? __ldg(&xr[64 + lane]) : 0.0f;
        float acc = 0.0f;
        int k = 0;
        for (; k < min(in_dim, 32); k++)
            acc = fmaf(__shfl_sync(0xffffffffu, xv0, k), ws[k * DIM + lane], acc);
        for (; k < min(in_dim, 64); k++)
            acc = fmaf(__shfl_sync(0xffffffffu, xv1, k - 32), ws[k * DIM + lane], acc);
        for (; k < in_dim; k++)
            acc = fmaf(__shfl_sync(0xffffffffu, xv2, k - 64), ws[k * DIM + lane], acc);
        g_p0[n * DIM + lane] = __float2half(acc);
    }
}

// ---------------- fused GIN layer (R2 champion form, bucket-indexed) ---------
// Input:  p_in[n] = h_l[n] @ Wa_l  (half)
// Output: p_out[n] = relu(relu(segsum + self + Ba) @ Wb + Bb) @ Wa_next (half)
// Edges for node n: g_bucket[n*CAP .. n*CAP + min(g_cnt[n],CAP)).
// If LAST: accumulate pooled sum of u into g_pool and reset g_cnt[n] to 0.
template <bool LAST>
__global__ void __launch_bounds__(256)
k_layer(const __half* __restrict__ p_in, __half* __restrict__ p_out,
        const float* __restrict__ Wb, const float* __restrict__ Bbv,
        const float* __restrict__ Bav, const float* __restrict__ Wanext,
        int n_nodes) {
    __shared__ float s_wb[DIM * DIM];
    __shared__ float s_wa[DIM * DIM];
    for (int i = threadIdx.x; i < DIM * DIM; i += blockDim.x) {
        s_wb[i] = Wb[i];
        if (!LAST) s_wa[i] = Wanext[i];
    }
    __syncthreads();

    const __half2* __restrict__ p2 = (const __half2*)p_in;
    int lane = threadIdx.x & 31;
    int half_id = lane >> 4;      // which edge of the pair this lane serves
    int fl = lane & 15;           // feature-pair index (features 2fl, 2fl+1)
    float ba_x = Bav[2 * fl], ba_y = Bav[2 * fl + 1];
    float bbv = Bbv[lane];

    int warp = (blockIdx.x * blockDim.x + threadIdx.x) >> 5;
    int nwarp = (gridDim.x * blockDim.x) >> 5;
    float pool = 0.0f;

    for (int n = warp; n < n_nodes; n += nwarp) {
        int cnt = g_cnt[n];
        if (LAST && lane == 0) g_cnt[n] = 0;  // restore entry invariant
        int deg = min(cnt, CAP);
        int beg = n * CAP;
        int end = beg + deg;

        float ax0 = 0.f, ay0 = 0.f, ax1 = 0.f, ay1 = 0.f;
        float ax2 = 0.f, ay2 = 0.f, ax3 = 0.f, ay3 = 0.f;
        float ax4 = 0.f, ay4 = 0.f, ax5 = 0.f, ay5 = 0.f;
        float ax6 = 0.f, ay6 = 0.f, ax7 = 0.f, ay7 = 0.f;
        int e = beg;
        // 16 edges per iteration: 8 independent half2 gathers per lane,
        // each warp-load covers 2 source rows (64B each).
        for (; e + 16 <= end; e += 16) {
            int s0 = g_bucket[e + 0 + half_id];
            int s1 = g_bucket[e + 2 + half_id];
            int s2 = g_bucket[e + 4 + half_id];
            int s3 = g_bucket[e + 6 + half_id];
            int s4 = g_bucket[e + 8 + half_id];
            int s5 = g_bucket[e + 10 + half_id];
            int s6 = g_bucket[e + 12 + half_id];
            int s7 = g_bucket[e + 14 + half_id];
            float2 f0 = __half22float2(p2[s0 * 16 + fl]);
            float2 f1 = __half22float2(p2[s1 * 16 + fl]);
            float2 f2 = __half22float2(p2[s2 * 16 + fl]);
            float2 f3 = __half22float2(p2[s3 * 16 + fl]);
            float2 f4 = __half22float2(p2[s4 * 16 + fl]);
            float2 f5 = __half22float2(p2[s5 * 16 + fl]);
            float2 f6 = __half22float2(p2[s6 * 16 + fl]);
            float2 f7 = __half22float2(p2[s7 * 16 + fl]);
            ax0 += f0.x; ay0 += f0.y;
            ax1 += f1.x; ay1 += f1.y;
            ax2 += f2.x; ay2 += f2.y;
            ax3 += f3.x; ay3 += f3.y;
            ax4 += f4.x; ay4 += f4.y;
            ax5 += f5.x; ay5 += f5.y;
            ax6 += f6.x; ay6 += f6.y;
            ax7 += f7.x; ay7 += f7.y;
        }
        // 2-edge remainder
        for (; e + 2 <= end; e += 2) {
            int s = g_bucket[e + half_id];
            float2 f = __half22float2(p2[s * 16 + fl]);
            ax0 += f.x; ay0 += f.y;
        }
        // single-edge remainder: lower half-warp only
        if (e < end && half_id == 0) {
            int s = g_bucket[e];
            float2 f = __half22float2(p2[s * 16 + fl]);
            ax0 += f.x; ay0 += f.y;
        }

        float tx = ((ax0 + ax1) + (ax2 + ax3)) + ((ax4 + ax5) + (ax6 + ax7));
        float ty = ((ay0 + ay1) + (ay2 + ay3)) + ((ay4 + ay5) + (ay6 + ay7));
        // combine the two half-warps' partials
        tx += __shfl_xor_sync(0xffffffffu, tx, 16);
        ty += __shfl_xor_sync(0xffffffffu, ty, 16);
        // self term + bias + relu (consistent across both halves)
        float2 sv = __half22float2(p2[n * 16 + fl]);
        tx = fmaxf(tx + sv.x + ba_x, 0.0f);
        ty = fmaxf(ty + sv.y + ba_y, 0.0f);

        // u_j = relu(sum_k t_k * Wb[k][j] + Bb[j]); j = lane
        float u = bbv;
#pragma unroll
        for (int k = 0; k < 16; k++) {
            float tkx = __shfl_sync(0xffffffffu, tx, k);
            float tky = __shfl_sync(0xffffffffu, ty, k);
            u = fmaf(tkx, s_wb[(2 * k) * DIM + lane], u);
            u = fmaf(tky, s_wb[(2 * k + 1) * DIM + lane], u);
        }
        u = fmaxf(u, 0.0f);

        if (!LAST) {
            float o = 0.0f;
#pragma unroll
            for (int k = 0; k < DIM; k++)
                o = fmaf(__shfl_sync(0xffffffffu, u, k), s_wa[k * DIM + lane], o);
            p_out[n * DIM + lane] = __float2half(o);
        } else {
            pool += u;
        }
    }

    if (LAST) {
        __shared__ float sp[8][DIM];
        int w = threadIdx.x >> 5;
        sp[w][lane] = pool;
        __syncthreads();
        if (w == 0) {
            float s = 0.0f;
#pragma unroll
            for (int i = 0; i < 8; i++) s += sp[i][lane];
            atomicAdd(&g_pool[lane], s);
        }
    }
}

// ---------------- head: consumes g_pool, then RESETS it for next call --------
__global__ void k_head(const float* __restrict__ fcw, const float* __restrict__ fcb,
                       const float* __restrict__ outw, const float* __restrict__ outb,
                       float* __restrict__ out) {
    __shared__ float g2[DIM];
    __shared__ float gp[DIM];
    int j = threadIdx.x;
    float pv = g_pool[j];
    g_pool[j] = 0.0f;   // restore invariant for next kernel_launch call
    gp[j] = pv;
    __syncwarp();
    float acc = fcb[j];
    for (int k = 0; k < DIM; k++) acc = fmaf(gp[k], fcw[k * DIM + j], acc);
    g2[j] = fmaxf(acc, 0.0f);
    __syncwarp();
    float o = outb[j];
    for (int k = 0; k < DIM; k++) o = fmaf(g2[k], outw[k * DIM + j], o);
    out[j] = o;
}

// ---------------- launch ------------------------------------------------------
extern "C" void kernel_launch(void* const* d_in, const int* in_sizes, int n_in,
                              void* d_out, int out_size) {
    const float* x    = (const float*)d_in[0];
    const int*   ei   = (const int*)d_in[1];
    const float* w1a  = (const float*)d_in[2];
    const float* b1a  = (const float*)d_in[3];
    const float* w1b  = (const float*)d_in[4];
    const float* b1b  = (const float*)d_in[5];
    const float* wa   = (const float*)d_in[6];
    const float* ba   = (const float*)d_in[7];
    const float* wb   = (const float*)d_in[8];
    const float* bb   = (const float*)d_in[9];
    const float* fcw  = (const float*)d_in[10];
    const float* fcb  = (const float*)d_in[11];
    const float* outw = (const float*)d_in[12];
    const float* outb = (const float*)d_in[13];

    int in_dim  = in_sizes[2] / DIM;           // w1a is (in_dim, 32)
    int n_nodes = in_sizes[0] / in_dim;        // x is (n, in_dim)
    int n_edges = in_sizes[1] / 2;             // edge_index is (2, E)
    const int* src = ei;
    const int* dst = ei + n_edges;

    __half *p0, *p1;
    cudaGetSymbolAddress((void**)&p0, g_p0);
    cudaGetSymbolAddress((void**)&p1, g_p1);

    // one-pass bucket build (g_cnt arrives zeroed; last layer re-zeroes it)
    k_fillb<<<2048, 256>>>(src, dst, n_edges);

    // projection to first-layer pre-aggregation space
    k_proj<<<1024, 256>>>(x, w1a, n_nodes, in_dim);

    // 5 fused GIN layers (double-buffered p)
    k_layer<false><<<2048, 256>>>(p0, p1, w1b, b1b, b1a, wa + 0 * DIM * DIM, n_nodes);
    k_layer<false><<<2048, 256>>>(p1, p0, wb + 0 * DIM * DIM, bb + 0 * DIM, ba + 0 * DIM,
                                  wa + 1 * DIM * DIM, n_nodes);
    k_layer<false><<<2048, 256>>>(p0, p1, wb + 1 * DIM * DIM, bb + 1 * DIM, ba + 1 * DIM,
                                  wa + 2 * DIM * DIM, n_nodes);
    k_layer<false><<<2048, 256>>>(p1, p0, wb + 2 * DIM * DIM, bb + 2 * DIM, ba + 2 * DIM,
                                  wa + 3 * DIM * DIM, n_nodes);
    k_layer<true><<<2048, 256>>>(p0, nullptr, wb + 3 * DIM * DIM, bb + 3 * DIM,
                                 ba + 3 * DIM, nullptr, n_nodes);

    // graph head (also resets g_pool)
    k_head<<<1, 32>>>(fcw, fcb, outw, outb, (float*)d_out);
}

// round 8
// speedup vs baseline: 1.2079x; 1.2079x over previous
#include <cuda_runtime.h>
#include <cuda_fp16.h>

#define DIM 32
#define NODES_MAX 100000
#define EDGES_MAX 3200000
#define SCAN_BLK 1024
#define NB_MAX 128   // ceil(100000/1024)=98

// ---------------- scratch (device globals; no allocation allowed) ------------
// Invariant at entry: g_deg all-zero, g_pool all-zero (zero at load;
// k_scan1 / k_head restore them every call).
// Row NODES_MAX of g_p0/g_p1 is a permanent ZERO row (sentinel for masked
// gathers) — never written by any kernel.
__device__ __half g_p0[(NODES_MAX + 1) * DIM];
__device__ __half g_p1[(NODES_MAX + 1) * DIM];
__device__ int    g_deg[NODES_MAX];
__device__ int    g_row[NODES_MAX + 1];
__device__ int    g_wcur[NODES_MAX];
__device__ int    g_ssrc[EDGES_MAX];
__device__ int    g_bsum[NB_MAX];
__device__ float  g_pool[DIM];

// ---------------- CSR build --------------------------------------------------
__global__ void k_hist(const int* __restrict__ dst, int n_edges) {
    int stride = gridDim.x * blockDim.x;
    for (int i = blockIdx.x * blockDim.x + threadIdx.x; i < n_edges; i += stride)
        atomicAdd(&g_deg[__ldg(&dst[i])], 1);
}

// Block-local exclusive scan of degrees; also RESETS g_deg for the next call.
__global__ void k_scan1(int n_nodes) {
    __shared__ int s[SCAN_BLK];
    int tid = threadIdx.x;
    int i = blockIdx.x * SCAN_BLK + tid;
    int v = 0;
    if (i < n_nodes) { v = g_deg[i]; g_deg[i] = 0; }
    s[tid] = v;
    __syncthreads();
    for (int off = 1; off < SCAN_BLK; off <<= 1) {
        int t = (tid >= off) ? s[tid - off] : 0;
        __syncthreads();
        s[tid] += t;
        __syncthreads();
    }
    if (i < n_nodes) g_row[i] = s[tid] - v;  // local exclusive
    if (tid == SCAN_BLK - 1) g_bsum[blockIdx.x] = s[tid];
}

// Cross-block offsets (block sums scanned locally in smem) + init g_wcur.
__global__ void k_scan3(int n_nodes, int n_edges, int nb) {
    __shared__ int sb[NB_MAX];
    __shared__ int sex[NB_MAX];
    int tid = threadIdx.x;
    int v = 0;
    if (tid < NB_MAX) {
        v = (tid < nb) ? g_bsum[tid] : 0;
        sb[tid] = v;
    }
    __syncthreads();
    for (int off = 1; off < NB_MAX; off <<= 1) {
        int t = 0;
        if (tid < NB_MAX && tid >= off) t = sb[tid - off];
        __syncthreads();
        if (tid < NB_MAX) sb[tid] += t;
        __syncthreads();
    }
    if (tid < NB_MAX) sex[tid] = sb[tid] - v;
    __syncthreads();

    int stride = gridDim.x * blockDim.x;
    int gid = blockIdx.x * blockDim.x + tid;
    for (int i = gid; i < n_nodes; i += stride) {
        int r = g_row[i] + sex[i / SCAN_BLK];
        g_row[i] = r;
        g_wcur[i] = r;
    }
    if (gid == 0) g_row[n_nodes] = n_edges;
}

__global__ void k_fill(const int* __restrict__ src, const int* __restrict__ dst,
                       int n_edges) {
    int stride = gridDim.x * blockDim.x;
    for (int i = blockIdx.x * blockDim.x + threadIdx.x; i < n_edges; i += stride) {
        int pos = atomicAdd(&g_wcur[__ldg(&dst[i])], 1);
        g_ssrc[pos] = __ldg(&src[i]);
    }
}

// ---------------- input projection: p0 = x @ w1a (half output) ---------------
__global__ void k_proj(const float* __restrict__ x, const float* __restrict__ w1a,
                       int n_nodes, int in_dim) {
    __shared__ float ws[96 * DIM];
    for (int i = threadIdx.x; i < in_dim * DIM; i += blockDim.x) ws[i] = w1a[i];
    __syncthreads();
    int lane = threadIdx.x & 31;
    int warp = (blockIdx.x * blockDim.x + threadIdx.x) >> 5;
    int nwarp = (gridDim.x * blockDim.x) >> 5;
    for (int n = warp; n < n_nodes; n += nwarp) {
        const float* xr = x + (size_t)n * in_dim;
        float xv0 = (lane < in_dim) ? __ldg(&xr[lane]) : 0.0f;
        float xv1 = (32 + lane < in_dim) ? __ldg(&xr[32 + lane]) : 0.0f;
        float xv2 = (64 + lane < in_dim) ? __ldg(&xr[64 + lane]) : 0.0f;
        float acc = 0.0f;
        int k = 0;
        for (; k < min(in_dim, 32); k++)
            acc = fmaf(__shfl_sync(0xffffffffu, xv0, k), ws[k * DIM + lane], acc);
        for (; k < min(in_dim, 64); k++)
            acc = fmaf(__shfl_sync(0xffffffffu, xv1, k - 32), ws[k * DIM + lane], acc);
        for (; k < in_dim; k++)
            acc = fmaf(__shfl_sync(0xffffffffu, xv2, k - 64), ws[k * DIM + lane], acc);
        g_p0[n * DIM + lane] = __float2half(acc);
    }
}

// ---------------- fused GIN layer: HADD2 acc, 4 edges/load, sentinel mask ----
// lane = quad*8+fq: quad in {0..3} = which edge of a 4-edge load, fq in {0..7}
// = feature quad (features 4fq..4fq+3 as one uint2 = 2 half2).
// Out-of-range gather positions redirect to the zero sentinel row (n_nodes).
template <bool LAST>
__global__ void __launch_bounds__(256)
k_layer(const __half* __restrict__ p_in, __half* __restrict__ p_out,
        const float* __restrict__ Wb, const float* __restrict__ Bbv,
        const float* __restrict__ Bav, const float* __restrict__ Wanext,
        int n_nodes) {
    __shared__ float s_wb[DIM * DIM];
    __shared__ float s_wa[DIM * DIM];
    for (int i = threadIdx.x; i < DIM * DIM; i += blockDim.x) {
        s_wb[i] = Wb[i];
        if (!LAST) s_wa[i] = Wanext[i];
    }
    __syncthreads();

    const uint2* __restrict__ pu = (const uint2*)p_in;  // row = 8 uint2
    int lane = threadIdx.x & 31;
    int quad = lane >> 3;
    int fq   = lane & 7;
    float4 ba4 = __ldg(&((const float4*)Bav)[fq]);
    float bbv = Bbv[lane];

    int warp = (blockIdx.x * blockDim.x + threadIdx.x) >> 5;
    int nwarp = (gridDim.x * blockDim.x) >> 5;
    float pool = 0.0f;

    const __half2 HZERO = __float2half2_rn(0.0f);

    // software-pipelined row pointers
    int n = warp;
    int rb = 0, re = 0;
    if (n < n_nodes) { rb = __ldg(&g_row[n]); re = __ldg(&g_row[n + 1]); }

    while (n < n_nodes) {
        int beg = rb, end = re;
        int nn = n + nwarp;
        if (nn < n_nodes) { rb = __ldg(&g_row[nn]); re = __ldg(&g_row[nn + 1]); }

        uint2 svu = pu[n * 8 + fq];  // self row in flight early

        __half2 l0 = HZERO, l1 = HZERO, l2 = HZERO, l3 = HZERO;
        __half2 l4 = HZERO, l5 = HZERO, l6 = HZERO, l7 = HZERO;
        __half2 h0 = HZERO, h1 = HZERO, h2 = HZERO, h3 = HZERO;
        __half2 h4 = HZERO, h5 = HZERO, h6 = HZERO, h7 = HZERO;

        int lim = end - 1;
        for (int base = beg; base < end; base += 32) {
#define G(M, LM, HM)                                                           \
            {                                                                  \
                int pos = base + 4 * (M) + quad;                               \
                int s = __ldg(&g_ssrc[min(pos, lim)]);                         \
                s = (pos < end) ? s : n_nodes;  /* sentinel zero row */        \
                uint2 v = pu[s * 8 + fq];                                      \
                LM = __hadd2(LM, *(__half2*)&v.x);                             \
                HM = __hadd2(HM, *(__half2*)&v.y);                             \
            }
            G(0, l0, h0) G(1, l1, h1) G(2, l2, h2) G(3, l3, h3)
            G(4, l4, h4) G(5, l5, h5) G(6, l6, h6) G(7, l7, h7)
#undef G
        }

        // one fp16 tree level (pairs of <=deg/8-sums), then fp32
        __half2 la = __hadd2(l0, l1), lb = __hadd2(l2, l3);
        __half2 lc = __hadd2(l4, l5), ld = __hadd2(l6, l7);
        __half2 ha = __hadd2(h0, h1), hb = __hadd2(h2, h3);
        __half2 hc = __hadd2(h4, h5), hd = __hadd2(h6, h7);
        float2 fa = __half22float2(la), fb = __half22float2(lb);
        float2 fc = __half22float2(lc), fd = __half22float2(ld);
        float2 ga = __half22float2(ha), gb = __half22float2(hb);
        float2 gc = __half22float2(hc), gd = __half22float2(hd);
        float t0 = (fa.x + fb.x) + (fc.x + fd.x);
        float t1 = (fa.y + fb.y) + (fc.y + fd.y);
        float t2 = (ga.x + gb.x) + (gc.x + gd.x);
        float t3 = (ga.y + gb.y) + (gc.y + gd.y);

        // reduce across the 4 quads (lanes l, l^8, l^16, l^24)
        t0 += __shfl_xor_sync(0xffffffffu, t0, 8);
        t1 += __shfl_xor_sync(0xffffffffu, t1, 8);
        t2 += __shfl_xor_sync(0xffffffffu, t2, 8);
        t3 += __shfl_xor_sync(0xffffffffu, t3, 8);
        t0 += __shfl_xor_sync(0xffffffffu, t0, 16);
        t1 += __shfl_xor_sync(0xffffffffu, t1, 16);
        t2 += __shfl_xor_sync(0xffffffffu, t2, 16);
        t3 += __shfl_xor_sync(0xffffffffu, t3, 16);

        // self + bias + relu
        float2 slo = __half22float2(*(__half2*)&svu.x);
        float2 shi = __half22float2(*(__half2*)&svu.y);
        t0 = fmaxf(t0 + slo.x + ba4.x, 0.0f);
        t1 = fmaxf(t1 + slo.y + ba4.y, 0.0f);
        t2 = fmaxf(t2 + shi.x + ba4.z, 0.0f);
        t3 = fmaxf(t3 + shi.y + ba4.w, 0.0f);

        // u_j = relu(sum_k t_k Wb[k][j] + Bb[j]); t_{4f+r} lives in lane f
        float u = bbv;
#pragma unroll
        for (int f = 0; f < 8; f++) {
            float c0 = __shfl_sync(0xffffffffu, t0, f);
            float c1 = __shfl_sync(0xffffffffu, t1, f);
            float c2 = __shfl_sync(0xffffffffu, t2, f);
            float c3 = __shfl_sync(0xffffffffu, t3, f);
            u = fmaf(c0, s_wb[(4 * f + 0) * DIM + lane], u);
            u = fmaf(c1, s_wb[(4 * f + 1) * DIM + lane], u);
            u = fmaf(c2, s_wb[(4 * f + 2) * DIM + lane], u);
            u = fmaf(c3, s_wb[(4 * f + 3) * DIM + lane], u);
        }
        u = fmaxf(u, 0.0f);

        if (!LAST) {
            float o = 0.0f;
#pragma unroll
            for (int k = 0; k < DIM; k++)
                o = fmaf(__shfl_sync(0xffffffffu, u, k), s_wa[k * DIM + lane], o);
            p_out[n * DIM + lane] = __float2half(o);
        } else {
            pool += u;
        }

        n = nn;
    }

    if (LAST) {
        __shared__ float sp[8][DIM];
        int w = threadIdx.x >> 5;
        sp[w][lane] = pool;
        __syncthreads();
        if (w == 0) {
            float s = 0.0f;
#pragma unroll
            for (int i = 0; i < 8; i++) s += sp[i][lane];
            atomicAdd(&g_pool[lane], s);
        }
    }
}

// ---------------- head: consumes g_pool, then RESETS it for next call --------
__global__ void k_head(const float* __restrict__ fcw, const float* __restrict__ fcb,
                       const float* __restrict__ outw, const float* __restrict__ outb,
                       float* __restrict__ out) {
    __shared__ float g2[DIM];
    __shared__ float gp[DIM];
    int j = threadIdx.x;
    float pv = g_pool[j];
    g_pool[j] = 0.0f;
    gp[j] = pv;
    __syncwarp();
    float acc = fcb[j];
    for (int k = 0; k < DIM; k++) acc = fmaf(gp[k], fcw[k * DIM + j], acc);
    g2[j] = fmaxf(acc, 0.0f);
    __syncwarp();
    float o = outb[j];
    for (int k = 0; k < DIM; k++) o = fmaf(g2[k], outw[k * DIM + j], o);
    out[j] = o;
}

// ---------------- launch ------------------------------------------------------
extern "C" void kernel_launch(void* const* d_in, const int* in_sizes, int n_in,
                              void* d_out, int out_size) {
    const float* x    = (const float*)d_in[0];
    const int*   ei   = (const int*)d_in[1];
    const float* w1a  = (const float*)d_in[2];
    const float* b1a  = (const float*)d_in[3];
    const float* w1b  = (const float*)d_in[4];
    const float* b1b  = (const float*)d_in[5];
    const float* wa   = (const float*)d_in[6];
    const float* ba   = (const float*)d_in[7];
    const float* wb   = (const float*)d_in[8];
    const float* bb   = (const float*)d_in[9];
    const float* fcw  = (const float*)d_in[10];
    const float* fcb  = (const float*)d_in[11];
    const float* outw = (const float*)d_in[12];
    const float* outb = (const float*)d_in[13];

    int in_dim  = in_sizes[2] / DIM;           // w1a is (in_dim, 32)
    int n_nodes = in_sizes[0] / in_dim;        // x is (n, in_dim)
    int n_edges = in_sizes[1] / 2;             // edge_index is (2, E)
    const int* src = ei;
    const int* dst = ei + n_edges;

    __half *p0, *p1;
    cudaGetSymbolAddress((void**)&p0, g_p0);
    cudaGetSymbolAddress((void**)&p1, g_p1);

    // CSR build (g_deg arrives zeroed; scan1 re-zeroes it)
    k_hist<<<2048, 256>>>(dst, n_edges);
    int nb = (n_nodes + SCAN_BLK - 1) / SCAN_BLK;
    k_scan1<<<nb, SCAN_BLK>>>(n_nodes);
    k_scan3<<<256, 256>>>(n_nodes, n_edges, nb);
    k_fill<<<2048, 256>>>(src, dst, n_edges);

    // projection to first-layer pre-aggregation space
    k_proj<<<1024, 256>>>(x, w1a, n_nodes, in_dim);

    // 5 fused GIN layers (double-buffered p)
    k_layer<false><<<2048, 256>>>(p0, p1, w1b, b1b, b1a, wa + 0 * DIM * DIM, n_nodes);
    k_layer<false><<<2048, 256>>>(p1, p0, wb + 0 * DIM * DIM, bb + 0 * DIM, ba + 0 * DIM,
                                  wa + 1 * DIM * DIM, n_nodes);
    k_layer<false><<<2048, 256>>>(p0, p1, wb + 1 * DIM * DIM, bb + 1 * DIM, ba + 1 * DIM,
                                  wa + 2 * DIM * DIM, n_nodes);
    k_layer<false><<<2048, 256>>>(p1, p0, wb + 2 * DIM * DIM, bb + 2 * DIM, ba + 2 * DIM,
                                  wa + 3 * DIM * DIM, n_nodes);
    k_layer<true><<<2048, 256>>>(p0, nullptr, wb + 3 * DIM * DIM, bb + 3 * DIM,
                                 ba + 3 * DIM, nullptr, n_nodes);

    // graph head (also resets g_pool)
    k_head<<<1, 32>>>(fcw, fcb, outw, outb, (float*)d_out);
}

// round 11
// speedup vs baseline: 1.6672x; 1.3803x over previous
#include <cuda_runtime.h>
#include <cuda_fp16.h>
#include <cstdint>

#define DIM 32
#define NODES_MAX 100000
#define EDGES_MAX 3200000
#define SCAN_BLK 1024
#define NB_MAX 128   // ceil(100000/1024)=98

// ---------------- scratch (device globals; no allocation allowed) ------------
// Invariant at entry: g_deg all-zero, g_pool all-zero (zero at load;
// k_scan1 / k_head restore them every call).
__device__ __half g_p0[NODES_MAX * DIM];
__device__ __half g_p1[NODES_MAX * DIM];
__device__ __half g_t[(NODES_MAX + 16) * DIM];   // agg output (padded tile)
__device__ int    g_deg[NODES_MAX];
__device__ int    g_row[NODES_MAX + 1];
__device__ int    g_wcur[NODES_MAX];
__device__ int    g_ssrc[EDGES_MAX];
__device__ int    g_bsum[NB_MAX];
__device__ float  g_pool[DIM];

// ---------------- CSR build --------------------------------------------------
__global__ void k_hist(const int* __restrict__ dst, int n_edges) {
    int stride = gridDim.x * blockDim.x;
    for (int i = blockIdx.x * blockDim.x + threadIdx.x; i < n_edges; i += stride)
        atomicAdd(&g_deg[__ldg(&dst[i])], 1);
}

__global__ void k_scan1(int n_nodes) {
    __shared__ int s[SCAN_BLK];
    int tid = threadIdx.x;
    int i = blockIdx.x * SCAN_BLK + tid;
    int v = 0;
    if (i < n_nodes) { v = g_deg[i]; g_deg[i] = 0; }
    s[tid] = v;
    __syncthreads();
    for (int off = 1; off < SCAN_BLK; off <<= 1) {
        int t = (tid >= off) ? s[tid - off] : 0;
        __syncthreads();
        s[tid] += t;
        __syncthreads();
    }
    if (i < n_nodes) g_row[i] = s[tid] - v;
    if (tid == SCAN_BLK - 1) g_bsum[blockIdx.x] = s[tid];
}

__global__ void k_scan3(int n_nodes, int n_edges, int nb) {
    __shared__ int sb[NB_MAX];
    __shared__ int sex[NB_MAX];
    int tid = threadIdx.x;
    int v = 0;
    if (tid < NB_MAX) {
        v = (tid < nb) ? g_bsum[tid] : 0;
        sb[tid] = v;
    }
    __syncthreads();
    for (int off = 1; off < NB_MAX; off <<= 1) {
        int t = 0;
        if (tid < NB_MAX && tid >= off) t = sb[tid - off];
        __syncthreads();
        if (tid < NB_MAX) sb[tid] += t;
        __syncthreads();
    }
    if (tid < NB_MAX) sex[tid] = sb[tid] - v;
    __syncthreads();

    int stride = gridDim.x * blockDim.x;
    int gid = blockIdx.x * blockDim.x + tid;
    for (int i = gid; i < n_nodes; i += stride) {
        int r = g_row[i] + sex[i / SCAN_BLK];
        g_row[i] = r;
        g_wcur[i] = r;
    }
    if (gid == 0) g_row[n_nodes] = n_edges;
}

__global__ void k_fill(const int* __restrict__ src, const int* __restrict__ dst,
                       int n_edges) {
    int stride = gridDim.x * blockDim.x;
    for (int i = blockIdx.x * blockDim.x + threadIdx.x; i < n_edges; i += stride) {
        int pos = atomicAdd(&g_wcur[__ldg(&dst[i])], 1);
        g_ssrc[pos] = __ldg(&src[i]);
    }
}

// ---------------- input projection: p0 = x @ w1a (half output) ---------------
__global__ void k_proj(const float* __restrict__ x, const float* __restrict__ w1a,
                       int n_nodes, int in_dim) {
    __shared__ float ws[96 * DIM];
    for (int i = threadIdx.x; i < in_dim * DIM; i += blockDim.x) ws[i] = w1a[i];
    __syncthreads();
    int lane = threadIdx.x & 31;
    int warp = (blockIdx.x * blockDim.x + threadIdx.x) >> 5;
    int nwarp = (gridDim.x * blockDim.x) >> 5;
    for (int n = warp; n < n_nodes; n += nwarp) {
        const float* xr = x + (size_t)n * in_dim;
        float xv0 = (lane < in_dim) ? __ldg(&xr[lane]) : 0.0f;
        float xv1 = (32 + lane < in_dim) ? __ldg(&xr[32 + lane]) : 0.0f;
        float xv2 = (64 + lane < in_dim) ? __ldg(&xr[64 + lane]) : 0.0f;
        float acc = 0.0f;
        int k = 0;
        for (; k < min(in_dim, 32); k++)
            acc = fmaf(__shfl_sync(0xffffffffu, xv0, k), ws[k * DIM + lane], acc);
        for (; k < min(in_dim, 64); k++)
            acc = fmaf(__shfl_sync(0xffffffffu, xv1, k - 32), ws[k * DIM + lane], acc);
        for (; k < in_dim; k++)
            acc = fmaf(__shfl_sync(0xffffffffu, xv2, k - 64), ws[k * DIM + lane], acc);
        g_p0[n * DIM + lane] = __float2half(acc);
    }
}

// ---------------- aggregation: t[n] = relu(sum_src p[src] + p[n] + Ba) -------
// R2-champion gather: 1 node/warp, 2 edges per half2 warp-load.
__global__ void __launch_bounds__(256)
k_agg(const __half* __restrict__ p_in, const float* __restrict__ Bav, int n_nodes) {
    const __half2* __restrict__ p2 = (const __half2*)p_in;
    __half2* __restrict__ t2 = (__half2*)g_t;
    int lane = threadIdx.x & 31;
    int half_id = lane >> 4;
    int fl = lane & 15;
    float ba_x = Bav[2 * fl], ba_y = Bav[2 * fl + 1];

    int warp = (blockIdx.x * blockDim.x + threadIdx.x) >> 5;
    int nwarp = (gridDim.x * blockDim.x) >> 5;

    for (int n = warp; n < n_nodes; n += nwarp) {
        int beg = g_row[n];
        int end = g_row[n + 1];

        float ax0 = 0.f, ay0 = 0.f, ax1 = 0.f, ay1 = 0.f;
        float ax2 = 0.f, ay2 = 0.f, ax3 = 0.f, ay3 = 0.f;
        float ax4 = 0.f, ay4 = 0.f, ax5 = 0.f, ay5 = 0.f;
        float ax6 = 0.f, ay6 = 0.f, ax7 = 0.f, ay7 = 0.f;
        int e = beg;
        for (; e + 16 <= end; e += 16) {
            int s0 = g_ssrc[e + 0 + half_id];
            int s1 = g_ssrc[e + 2 + half_id];
            int s2 = g_ssrc[e + 4 + half_id];
            int s3 = g_ssrc[e + 6 + half_id];
            int s4 = g_ssrc[e + 8 + half_id];
            int s5 = g_ssrc[e + 10 + half_id];
            int s6 = g_ssrc[e + 12 + half_id];
            int s7 = g_ssrc[e + 14 + half_id];
            float2 f0 = __half22float2(p2[s0 * 16 + fl]);
            float2 f1 = __half22float2(p2[s1 * 16 + fl]);
            float2 f2 = __half22float2(p2[s2 * 16 + fl]);
            float2 f3 = __half22float2(p2[s3 * 16 + fl]);
            float2 f4 = __half22float2(p2[s4 * 16 + fl]);
            float2 f5 = __half22float2(p2[s5 * 16 + fl]);
            float2 f6 = __half22float2(p2[s6 * 16 + fl]);
            float2 f7 = __half22float2(p2[s7 * 16 + fl]);
            ax0 += f0.x; ay0 += f0.y;
            ax1 += f1.x; ay1 += f1.y;
            ax2 += f2.x; ay2 += f2.y;
            ax3 += f3.x; ay3 += f3.y;
            ax4 += f4.x; ay4 += f4.y;
            ax5 += f5.x; ay5 += f5.y;
            ax6 += f6.x; ay6 += f6.y;
            ax7 += f7.x; ay7 += f7.y;
        }
        for (; e + 2 <= end; e += 2) {
            int s = g_ssrc[e + half_id];
            float2 f = __half22float2(p2[s * 16 + fl]);
            ax0 += f.x; ay0 += f.y;
        }
        if (e < end && half_id == 0) {
            int s = g_ssrc[e];
            float2 f = __half22float2(p2[s * 16 + fl]);
            ax0 += f.x; ay0 += f.y;
        }

        float tx = ((ax0 + ax1) + (ax2 + ax3)) + ((ax4 + ax5) + (ax6 + ax7));
        float ty = ((ay0 + ay1) + (ay2 + ay3)) + ((ay4 + ay5) + (ay6 + ay7));
        tx += __shfl_xor_sync(0xffffffffu, tx, 16);
        ty += __shfl_xor_sync(0xffffffffu, ty, 16);
        float2 sv = __half22float2(p2[n * 16 + fl]);
        tx = fmaxf(tx + sv.x + ba_x, 0.0f);
        ty = fmaxf(ty + sv.y + ba_y, 0.0f);

        if (half_id == 0) t2[n * 16 + fl] = __floats2half2_rn(tx, ty);
    }
}

// ---------------- MLP via HMMA: p_out = relu(t@Wb+Bb) @ Wa -------------------
// m16n8k16 fp16 mma, double-half weight splitting (Whi+Wlo) for precision.
// Warp processes a 16-node tile. Accumulator-of-GEMM1 repacks directly into
// A-fragments of GEMM2 (standard identity; no smem round trip).
__device__ __forceinline__ void mma16816(float& d0, float& d1, float& d2, float& d3,
                                         uint32_t a0, uint32_t a1, uint32_t a2,
                                         uint32_t a3, uint32_t b0, uint32_t b1) {
    asm volatile(
        "mma.sync.aligned.m16n8k16.row.col.f32.f16.f16.f32 "
        "{%0,%1,%2,%3}, {%4,%5,%6,%7}, {%8,%9}, {%0,%1,%2,%3};"
        : "+f"(d0), "+f"(d1), "+f"(d2), "+f"(d3)
        : "r"(a0), "r"(a1), "r"(a2), "r"(a3), "r"(b0), "r"(b1));
}

__device__ __forceinline__ uint32_t packh2(float x, float y) {
    __half2 h = __floats2half2_rn(x, y);
    return *(uint32_t*)&h;
}

template <bool LAST>
__global__ void __launch_bounds__(256)
k_mlp(__half* __restrict__ p_out, const float* __restrict__ Wb,
      const float* __restrict__ Bb, const float* __restrict__ Wa, int n_nodes) {
    int lane = threadIdx.x & 31;
    int bcol = lane >> 2;          // B-fragment column
    int kq   = (lane & 3) * 2;     // A/B k index base; also D column base
    int row  = lane >> 2;          // A/D row base

    // Build B fragments once (weights constant for the kernel).
    // [kt][nt][rr]: kt = k-tile (0,1), nt = n-tile (0..3), rr = reg (k, k+8)
    uint32_t bbh[2][4][2], bbl[2][4][2];
    uint32_t bah[2][4][2], bal[2][4][2];
#pragma unroll
    for (int kt = 0; kt < 2; kt++)
#pragma unroll
        for (int nt = 0; nt < 4; nt++)
#pragma unroll
            for (int rr = 0; rr < 2; rr++) {
                int k0 = kt * 16 + kq + rr * 8;
                int j = nt * 8 + bcol;
                float w0 = __ldg(&Wb[k0 * DIM + j]);
                float w1 = __ldg(&Wb[(k0 + 1) * DIM + j]);
                __half2 h = __floats2half2_rn(w0, w1);
                bbh[kt][nt][rr] = *(uint32_t*)&h;
                bbl[kt][nt][rr] = packh2(w0 - __low2float(h), w1 - __high2float(h));
                if (!LAST) {
                    float v0 = __ldg(&Wa[k0 * DIM + j]);
                    float v1 = __ldg(&Wa[(k0 + 1) * DIM + j]);
                    __half2 g = __floats2half2_rn(v0, v1);
                    bah[kt][nt][rr] = *(uint32_t*)&g;
                    bal[kt][nt][rr] = packh2(v0 - __low2float(g), v1 - __high2float(g));
                }
            }
    float bb0[4], bb1[4];
#pragma unroll
    for (int nt = 0; nt < 4; nt++) {
        bb0[nt] = __ldg(&Bb[nt * 8 + kq]);
        bb1[nt] = __ldg(&Bb[nt * 8 + kq + 1]);
    }

    float pacc0[4] = {0, 0, 0, 0}, pacc1[4] = {0, 0, 0, 0};
    __shared__ float ps[DIM];
    if (LAST) {
        if (threadIdx.x < DIM) ps[threadIdx.x] = 0.0f;
        __syncthreads();
    }

    const uint32_t* __restrict__ t32 = (const uint32_t*)g_t;
    uint32_t* __restrict__ po = (uint32_t*)p_out;

    int warp = (blockIdx.x * blockDim.x + threadIdx.x) >> 5;
    int nwarp = (gridDim.x * blockDim.x) >> 5;
    int n_tiles = (n_nodes + 15) >> 4;

    for (int tile = warp; tile < n_tiles; tile += nwarp) {
        int base = tile * 16;
        // A fragments of t (16x32): direct global loads
        uint32_t a[2][4];
#pragma unroll
        for (int kt = 0; kt < 2; kt++) {
            int o = kt * 8 + (lane & 3);
            a[kt][0] = t32[(base + row) * 16 + o];
            a[kt][1] = t32[(base + row + 8) * 16 + o];
            a[kt][2] = t32[(base + row) * 16 + o + 4];
            a[kt][3] = t32[(base + row + 8) * 16 + o + 4];
        }

        // GEMM1: d = t @ Wb  (hi + lo weight terms)
        float d[4][4];
#pragma unroll
        for (int nt = 0; nt < 4; nt++) { d[nt][0] = d[nt][1] = d[nt][2] = d[nt][3] = 0.f; }
#pragma unroll
        for (int kt = 0; kt < 2; kt++)
#pragma unroll
            for (int nt = 0; nt < 4; nt++) {
                mma16816(d[nt][0], d[nt][1], d[nt][2], d[nt][3],
                         a[kt][0], a[kt][1], a[kt][2], a[kt][3],
                         bbh[kt][nt][0], bbh[kt][nt][1]);
                mma16816(d[nt][0], d[nt][1], d[nt][2], d[nt][3],
                         a[kt][0], a[kt][1], a[kt][2], a[kt][3],
                         bbl[kt][nt][0], bbl[kt][nt][1]);
            }
        // u = relu(d + Bb)
        float u[4][4];
#pragma unroll
        for (int nt = 0; nt < 4; nt++) {
            u[nt][0] = fmaxf(d[nt][0] + bb0[nt], 0.f);
            u[nt][1] = fmaxf(d[nt][1] + bb1[nt], 0.f);
            u[nt][2] = fmaxf(d[nt][2] + bb0[nt], 0.f);
            u[nt][3] = fmaxf(d[nt][3] + bb1[nt], 0.f);
        }

        if (!LAST) {
            // repack accumulators as A-fragments of GEMM2
            uint32_t ua[2][4];
#pragma unroll
            for (int kt2 = 0; kt2 < 2; kt2++) {
                int s = kt2 * 2;
                ua[kt2][0] = packh2(u[s][0], u[s][1]);
                ua[kt2][1] = packh2(u[s][2], u[s][3]);
                ua[kt2][2] = packh2(u[s + 1][0], u[s + 1][1]);
                ua[kt2][3] = packh2(u[s + 1][2], u[s + 1][3]);
            }
            float e[4][4];
#pragma unroll
            for (int nt = 0; nt < 4; nt++) { e[nt][0] = e[nt][1] = e[nt][2] = e[nt][3] = 0.f; }
#pragma unroll
            for (int kt2 = 0; kt2 < 2; kt2++)
#pragma unroll
                for (int nt = 0; nt < 4; nt++) {
                    mma16816(e[nt][0], e[nt][1], e[nt][2], e[nt][3],
                             ua[kt2][0], ua[kt2][1], ua[kt2][2], ua[kt2][3],
                             bah[kt2][nt][0], bah[kt2][nt][1]);
                    mma16816(e[nt][0], e[nt][1], e[nt][2], e[nt][3],
                             ua[kt2][0], ua[kt2][1], ua[kt2][2], ua[kt2][3],
                             bal[kt2][nt][0], bal[kt2][nt][1]);
                }
            // store p_out rows
#pragma unroll
            for (int nt = 0; nt < 4; nt++) {
                po[(base + row) * 16 + nt * 4 + (lane & 3)] = packh2(e[nt][0], e[nt][1]);
                po[(base + row + 8) * 16 + nt * 4 + (lane & 3)] = packh2(e[nt][2], e[nt][3]);
            }
        } else {
            float m0 = (base + row < n_nodes) ? 1.0f : 0.0f;
            float m1 = (base + row + 8 < n_nodes) ? 1.0f : 0.0f;
#pragma unroll
            for (int nt = 0; nt < 4; nt++) {
                pacc0[nt] += m0 * u[nt][0] + m1 * u[nt][2];
                pacc1[nt] += m0 * u[nt][1] + m1 * u[nt][3];
            }
        }
    }

    if (LAST) {
#pragma unroll
        for (int nt = 0; nt < 4; nt++) {
            atomicAdd(&ps[nt * 8 + kq], pacc0[nt]);
            atomicAdd(&ps[nt * 8 + kq + 1], pacc1[nt]);
        }
        __syncthreads();
        if (threadIdx.x < DIM) atomicAdd(&g_pool[threadIdx.x], ps[threadIdx.x]);
    }
}

// ---------------- head: consumes g_pool, then RESETS it for next call --------
__global__ void k_head(const float* __restrict__ fcw, const float* __restrict__ fcb,
                       const float* __restrict__ outw, const float* __restrict__ outb,
                       float* __restrict__ out) {
    __shared__ float g2[DIM];
    __shared__ float gp[DIM];
    int j = threadIdx.x;
    float pv = g_pool[j];
    g_pool[j] = 0.0f;
    gp[j] = pv;
    __syncwarp();
    float acc = fcb[j];
    for (int k = 0; k < DIM; k++) acc = fmaf(gp[k], fcw[k * DIM + j], acc);
    g2[j] = fmaxf(acc, 0.0f);
    __syncwarp();
    float o = outb[j];
    for (int k = 0; k < DIM; k++) o = fmaf(g2[k], outw[k * DIM + j], o);
    out[j] = o;
}

// ---------------- launch ------------------------------------------------------
extern "C" void kernel_launch(void* const* d_in, const int* in_sizes, int n_in,
                              void* d_out, int out_size) {
    const float* x    = (const float*)d_in[0];
    const int*   ei   = (const int*)d_in[1];
    const float* w1a  = (const float*)d_in[2];
    const float* b1a  = (const float*)d_in[3];
    const float* w1b  = (const float*)d_in[4];
    const float* b1b  = (const float*)d_in[5];
    const float* wa   = (const float*)d_in[6];
    const float* ba   = (const float*)d_in[7];
    const float* wb   = (const float*)d_in[8];
    const float* bb   = (const float*)d_in[9];
    const float* fcw  = (const float*)d_in[10];
    const float* fcb  = (const float*)d_in[11];
    const float* outw = (const float*)d_in[12];
    const float* outb = (const float*)d_in[13];

    int in_dim  = in_sizes[2] / DIM;
    int n_nodes = in_sizes[0] / in_dim;
    int n_edges = in_sizes[1] / 2;
    const int* src = ei;
    const int* dst = ei + n_edges;

    __half *p0, *p1;
    cudaGetSymbolAddress((void**)&p0, g_p0);
    cudaGetSymbolAddress((void**)&p1, g_p1);

    // CSR build
    k_hist<<<2048, 256>>>(dst, n_edges);
    int nb = (n_nodes + SCAN_BLK - 1) / SCAN_BLK;
    k_scan1<<<nb, SCAN_BLK>>>(n_nodes);
    k_scan3<<<256, 256>>>(n_nodes, n_edges, nb);
    k_fill<<<2048, 256>>>(src, dst, n_edges);

    // projection
    k_proj<<<1024, 256>>>(x, w1a, n_nodes, in_dim);

    // 5 layers: agg (gather) + mlp (tensor-core GEMM chain)
    k_agg<<<2048, 256>>>(p0, b1a, n_nodes);
    k_mlp<false><<<256, 256>>>(p1, w1b, b1b, wa + 0 * DIM * DIM, n_nodes);

    k_agg<<<2048, 256>>>(p1, ba + 0 * DIM, n_nodes);
    k_mlp<false><<<256, 256>>>(p0, wb + 0 * DIM * DIM, bb + 0 * DIM,
                               wa + 1 * DIM * DIM, n_nodes);

    k_agg<<<2048, 256>>>(p0, ba + 1 * DIM, n_nodes);
    k_mlp<false><<<256, 256>>>(p1, wb + 1 * DIM * DIM, bb + 1 * DIM,
                               wa + 2 * DIM * DIM, n_nodes);

    k_agg<<<2048, 256>>>(p1, ba + 2 * DIM, n_nodes);
    k_mlp<false><<<256, 256>>>(p0, wb + 2 * DIM * DIM, bb + 2 * DIM,
                               wa + 3 * DIM * DIM, n_nodes);

    k_agg<<<2048, 256>>>(p0, ba + 3 * DIM, n_nodes);
    k_mlp<true><<<256, 256>>>(p1, wb + 3 * DIM * DIM, bb + 3 * DIM,
                              nullptr, n_nodes);

    // graph head (also resets g_pool)
    k_head<<<1, 32>>>(fcw, fcb, outw, outb, (float*)d_out);
}

// round 13
// speedup vs baseline: 1.7635x; 1.0578x over previous
#include <cuda_runtime.h>
#include <cuda_fp16.h>
#include <cstdint>

#define DIM 32
#define NODES_MAX 100000
#define EDGES_MAX 3200000
#define SCAN_BLK 1024
#define NB_MAX 128   // ceil(100000/1024)=98

#define PROJ_BLOCKS 1024
#define FILL_BLOCKS 2048

// ---------------- scratch (device globals; no allocation allowed) ------------
// Invariant at entry: g_deg all-zero, g_pool all-zero (zero at load;
// k_scan1 / k_head restore them every call).
// p buffers padded +16 rows: k_mlp's last partial 16-node tile writes whole rows.
__device__ __half g_p0[(NODES_MAX + 16) * DIM];
__device__ __half g_p1[(NODES_MAX + 16) * DIM];
__device__ __half g_t[(NODES_MAX + 16) * DIM];   // agg output (padded tile)
__device__ int    g_deg[NODES_MAX];
__device__ int    g_row[NODES_MAX + 1];
__device__ int    g_wcur[NODES_MAX];
__device__ int    g_ssrc[EDGES_MAX];
__device__ int    g_bsum[NB_MAX];
__device__ float  g_pool[DIM];

// ---------------- CSR build --------------------------------------------------
__global__ void k_hist(const int* __restrict__ dst, int n_edges) {
    int stride = gridDim.x * blockDim.x;
    int gid = blockIdx.x * blockDim.x + threadIdx.x;
    int n4 = n_edges >> 2;
    const int4* d4 = (const int4*)dst;
    for (int i = gid; i < n4; i += stride) {
        int4 v = __ldg(&d4[i]);
        atomicAdd(&g_deg[v.x], 1);
        atomicAdd(&g_deg[v.y], 1);
        atomicAdd(&g_deg[v.z], 1);
        atomicAdd(&g_deg[v.w], 1);
    }
    int base = n4 << 2;
    if (gid < (n_edges - base))
        atomicAdd(&g_deg[__ldg(&dst[base + gid])], 1);
}

__global__ void k_scan1(int n_nodes) {
    __shared__ int s[SCAN_BLK];
    int tid = threadIdx.x;
    int i = blockIdx.x * SCAN_BLK + tid;
    int v = 0;
    if (i < n_nodes) { v = g_deg[i]; g_deg[i] = 0; }
    s[tid] = v;
    __syncthreads();
    for (int off = 1; off < SCAN_BLK; off <<= 1) {
        int t = (tid >= off) ? s[tid - off] : 0;
        __syncthreads();
        s[tid] += t;
        __syncthreads();
    }
    if (i < n_nodes) g_row[i] = s[tid] - v;
    if (tid == SCAN_BLK - 1) g_bsum[blockIdx.x] = s[tid];
}

__global__ void k_scan3(int n_nodes, int n_edges, int nb) {
    __shared__ int sb[NB_MAX];
    __shared__ int sex[NB_MAX];
    int tid = threadIdx.x;
    int v = 0;
    if (tid < NB_MAX) {
        v = (tid < nb) ? g_bsum[tid] : 0;
        sb[tid] = v;
    }
    __syncthreads();
    for (int off = 1; off < NB_MAX; off <<= 1) {
        int t = 0;
        if (tid < NB_MAX && tid >= off) t = sb[tid - off];
        __syncthreads();
        if (tid < NB_MAX) sb[tid] += t;
        __syncthreads();
    }
    if (tid < NB_MAX) sex[tid] = sb[tid] - v;
    __syncthreads();

    int stride = gridDim.x * blockDim.x;
    int gid = blockIdx.x * blockDim.x + tid;
    for (int i = gid; i < n_nodes; i += stride) {
        int r = g_row[i] + sex[i / SCAN_BLK];
        g_row[i] = r;
        g_wcur[i] = r;
    }
    if (gid == 0) g_row[n_nodes] = n_edges;
}

// ---------------- fused fill + proj ------------------------------------------
// Blocks [0, PROJ_BLOCKS): p0 = half(x @ w1a).
// Blocks [PROJ_BLOCKS, PROJ_BLOCKS+FILL_BLOCKS): CSR fill (int4 edge reads).
// The two halves use complementary resources (FMA/smem vs atomics/scatter).
__global__ void __launch_bounds__(256)
k_fillproj(const int* __restrict__ src, const int* __restrict__ dst, int n_edges,
           const float* __restrict__ x, const float* __restrict__ w1a,
           int n_nodes, int in_dim) {
    __shared__ float ws[96 * DIM];
    if (blockIdx.x < PROJ_BLOCKS) {
        // ---- projection path ----
        for (int i = threadIdx.x; i < in_dim * DIM; i += blockDim.x) ws[i] = w1a[i];
        __syncthreads();
        int lane = threadIdx.x & 31;
        int warp = (blockIdx.x * blockDim.x + threadIdx.x) >> 5;
        int nwarp = (PROJ_BLOCKS * blockDim.x) >> 5;
        for (int n = warp; n < n_nodes; n += nwarp) {
            const float* xr = x + (size_t)n * in_dim;
            float xv0 = (lane < in_dim) ? __ldg(&xr[lane]) : 0.0f;
            float xv1 = (32 + lane < in_dim) ? __ldg(&xr[32 + lane]) : 0.0f;
            float xv2 = (64 + lane < in_dim) ? __ldg(&xr[64 + lane]) : 0.0f;
            float acc = 0.0f;
            int k = 0;
            for (; k < min(in_dim, 32); k++)
                acc = fmaf(__shfl_sync(0xffffffffu, xv0, k), ws[k * DIM + lane], acc);
            for (; k < min(in_dim, 64); k++)
                acc = fmaf(__shfl_sync(0xffffffffu, xv1, k - 32), ws[k * DIM + lane], acc);
            for (; k < in_dim; k++)
                acc = fmaf(__shfl_sync(0xffffffffu, xv2, k - 64), ws[k * DIM + lane], acc);
            g_p0[n * DIM + lane] = __float2half(acc);
        }
    } else {
        // ---- CSR fill path (int4 vectorized) ----
        int gid = (blockIdx.x - PROJ_BLOCKS) * blockDim.x + threadIdx.x;
        int stride = FILL_BLOCKS * blockDim.x;
        int n4 = n_edges >> 2;
        const int4* s4 = (const int4*)src;
        const int4* d4 = (const int4*)dst;
        for (int i = gid; i < n4; i += stride) {
            int4 d = __ldg(&d4[i]);
            int4 s = __ldg(&s4[i]);
            g_ssrc[atomicAdd(&g_wcur[d.x], 1)] = s.x;
            g_ssrc[atomicAdd(&g_wcur[d.y], 1)] = s.y;
            g_ssrc[atomicAdd(&g_wcur[d.z], 1)] = s.z;
            g_ssrc[atomicAdd(&g_wcur[d.w], 1)] = s.w;
        }
        int base = n4 << 2;
        if (gid < (n_edges - base)) {
            int i = base + gid;
            g_ssrc[atomicAdd(&g_wcur[__ldg(&dst[i])], 1)] = __ldg(&src[i]);
        }
    }
}

// ---------------- aggregation: t[n] = relu(sum_src p[src] + p[n] + Ba) -------
// R2-champion gather: 1 node/warp, 2 edges per half2 warp-load.
__global__ void __launch_bounds__(256)
k_agg(const __half* __restrict__ p_in, const float* __restrict__ Bav, int n_nodes) {
    const __half2* __restrict__ p2 = (const __half2*)p_in;
    __half2* __restrict__ t2 = (__half2*)g_t;
    int lane = threadIdx.x & 31;
    int half_id = lane >> 4;
    int fl = lane & 15;
    float ba_x = Bav[2 * fl], ba_y = Bav[2 * fl + 1];

    int warp = (blockIdx.x * blockDim.x + threadIdx.x) >> 5;
    int nwarp = (gridDim.x * blockDim.x) >> 5;

    for (int n = warp; n < n_nodes; n += nwarp) {
        int beg = g_row[n];
        int end = g_row[n + 1];

        float ax0 = 0.f, ay0 = 0.f, ax1 = 0.f, ay1 = 0.f;
        float ax2 = 0.f, ay2 = 0.f, ax3 = 0.f, ay3 = 0.f;
        float ax4 = 0.f, ay4 = 0.f, ax5 = 0.f, ay5 = 0.f;
        float ax6 = 0.f, ay6 = 0.f, ax7 = 0.f, ay7 = 0.f;
        int e = beg;
        for (; e + 16 <= end; e += 16) {
            int s0 = g_ssrc[e + 0 + half_id];
            int s1 = g_ssrc[e + 2 + half_id];
            int s2 = g_ssrc[e + 4 + half_id];
            int s3 = g_ssrc[e + 6 + half_id];
            int s4 = g_ssrc[e + 8 + half_id];
            int s5 = g_ssrc[e + 10 + half_id];
            int s6 = g_ssrc[e + 12 + half_id];
            int s7 = g_ssrc[e + 14 + half_id];
            float2 f0 = __half22float2(p2[s0 * 16 + fl]);
            float2 f1 = __half22float2(p2[s1 * 16 + fl]);
            float2 f2 = __half22float2(p2[s2 * 16 + fl]);
            float2 f3 = __half22float2(p2[s3 * 16 + fl]);
            float2 f4 = __half22float2(p2[s4 * 16 + fl]);
            float2 f5 = __half22float2(p2[s5 * 16 + fl]);
            float2 f6 = __half22float2(p2[s6 * 16 + fl]);
            float2 f7 = __half22float2(p2[s7 * 16 + fl]);
            ax0 += f0.x; ay0 += f0.y;
            ax1 += f1.x; ay1 += f1.y;
            ax2 += f2.x; ay2 += f2.y;
            ax3 += f3.x; ay3 += f3.y;
            ax4 += f4.x; ay4 += f4.y;
            ax5 += f5.x; ay5 += f5.y;
            ax6 += f6.x; ay6 += f6.y;
            ax7 += f7.x; ay7 += f7.y;
        }
        for (; e + 2 <= end; e += 2) {
            int s = g_ssrc[e + half_id];
            float2 f = __half22float2(p2[s * 16 + fl]);
            ax0 += f.x; ay0 += f.y;
        }
        if (e < end && half_id == 0) {
            int s = g_ssrc[e];
            float2 f = __half22float2(p2[s * 16 + fl]);
            ax0 += f.x; ay0 += f.y;
        }

        float tx = ((ax0 + ax1) + (ax2 + ax3)) + ((ax4 + ax5) + (ax6 + ax7));
        float ty = ((ay0 + ay1) + (ay2 + ay3)) + ((ay4 + ay5) + (ay6 + ay7));
        tx += __shfl_xor_sync(0xffffffffu, tx, 16);
        ty += __shfl_xor_sync(0xffffffffu, ty, 16);
        float2 sv = __half22float2(p2[n * 16 + fl]);
        tx = fmaxf(tx + sv.x + ba_x, 0.0f);
        ty = fmaxf(ty + sv.y + ba_y, 0.0f);

        if (half_id == 0) t2[n * 16 + fl] = __floats2half2_rn(tx, ty);
    }
}

// ---------------- MLP via HMMA: p_out = relu(t@Wb+Bb) @ Wa -------------------
__device__ __forceinline__ void mma16816(float& d0, float& d1, float& d2, float& d3,
                                         uint32_t a0, uint32_t a1, uint32_t a2,
                                         uint32_t a3, uint32_t b0, uint32_t b1) {
    asm volatile(
        "mma.sync.aligned.m16n8k16.row.col.f32.f16.f16.f32 "
        "{%0,%1,%2,%3}, {%4,%5,%6,%7}, {%8,%9}, {%0,%1,%2,%3};"
        : "+f"(d0), "+f"(d1), "+f"(d2), "+f"(d3)
        : "r"(a0), "r"(a1), "r"(a2), "r"(a3), "r"(b0), "r"(b1));
}

__device__ __forceinline__ uint32_t packh2(float x, float y) {
    __half2 h = __floats2half2_rn(x, y);
    return *(uint32_t*)&h;
}

template <bool LAST>
__global__ void __launch_bounds__(256)
k_mlp(__half* __restrict__ p_out, const float* __restrict__ Wb,
      const float* __restrict__ Bb, const float* __restrict__ Wa, int n_nodes) {
    int lane = threadIdx.x & 31;
    int bcol = lane >> 2;
    int kq   = (lane & 3) * 2;
    int row  = lane >> 2;

    uint32_t bbh[2][4][2], bbl[2][4][2];
    uint32_t bah[2][4][2], bal[2][4][2];
#pragma unroll
    for (int kt = 0; kt < 2; kt++)
#pragma unroll
        for (int nt = 0; nt < 4; nt++)
#pragma unroll
            for (int rr = 0; rr < 2; rr++) {
                int k0 = kt * 16 + kq + rr * 8;
                int j = nt * 8 + bcol;
                float w0 = __ldg(&Wb[k0 * DIM + j]);
                float w1 = __ldg(&Wb[(k0 + 1) * DIM + j]);
                __half2 h = __floats2half2_rn(w0, w1);
                bbh[kt][nt][rr] = *(uint32_t*)&h;
                bbl[kt][nt][rr] = packh2(w0 - __low2float(h), w1 - __high2float(h));
                if (!LAST) {
                    float v0 = __ldg(&Wa[k0 * DIM + j]);
                    float v1 = __ldg(&Wa[(k0 + 1) * DIM + j]);
                    __half2 g = __floats2half2_rn(v0, v1);
                    bah[kt][nt][rr] = *(uint32_t*)&g;
                    bal[kt][nt][rr] = packh2(v0 - __low2float(g), v1 - __high2float(g));
                }
            }
    float bb0[4], bb1[4];
#pragma unroll
    for (int nt = 0; nt < 4; nt++) {
        bb0[nt] = __ldg(&Bb[nt * 8 + kq]);
        bb1[nt] = __ldg(&Bb[nt * 8 + kq + 1]);
    }

    float pacc0[4] = {0, 0, 0, 0}, pacc1[4] = {0, 0, 0, 0};
    __shared__ float ps[DIM];
    if (LAST) {
        if (threadIdx.x < DIM) ps[threadIdx.x] = 0.0f;
        __syncthreads();
    }

    const uint32_t* __restrict__ t32 = (const uint32_t*)g_t;
    uint32_t* __restrict__ po = (uint32_t*)p_out;

    int warp = (blockIdx.x * blockDim.x + threadIdx.x) >> 5;
    int nwarp = (gridDim.x * blockDim.x) >> 5;
    int n_tiles = (n_nodes + 15) >> 4;

    for (int tile = warp; tile < n_tiles; tile += nwarp) {
        int base = tile * 16;
        uint32_t a[2][4];
#pragma unroll
        for (int kt = 0; kt < 2; kt++) {
            int o = kt * 8 + (lane & 3);
            a[kt][0] = t32[(base + row) * 16 + o];
            a[kt][1] = t32[(base + row + 8) * 16 + o];
            a[kt][2] = t32[(base + row) * 16 + o + 4];
            a[kt][3] = t32[(base + row + 8) * 16 + o + 4];
        }

        float d[4][4];
#pragma unroll
        for (int nt = 0; nt < 4; nt++) { d[nt][0] = d[nt][1] = d[nt][2] = d[nt][3] = 0.f; }
#pragma unroll
        for (int kt = 0; kt < 2; kt++)
#pragma unroll
            for (int nt = 0; nt < 4; nt++) {
                mma16816(d[nt][0], d[nt][1], d[nt][2], d[nt][3],
                         a[kt][0], a[kt][1], a[kt][2], a[kt][3],
                         bbh[kt][nt][0], bbh[kt][nt][1]);
                mma16816(d[nt][0], d[nt][1], d[nt][2], d[nt][3],
                         a[kt][0], a[kt][1], a[kt][2], a[kt][3],
                         bbl[kt][nt][0], bbl[kt][nt][1]);
            }
        float u[4][4];
#pragma unroll
        for (int nt = 0; nt < 4; nt++) {
            u[nt][0] = fmaxf(d[nt][0] + bb0[nt], 0.f);
            u[nt][1] = fmaxf(d[nt][1] + bb1[nt], 0.f);
            u[nt][2] = fmaxf(d[nt][2] + bb0[nt], 0.f);
            u[nt][3] = fmaxf(d[nt][3] + bb1[nt], 0.f);
        }

        if (!LAST) {
            uint32_t ua[2][4];
#pragma unroll
            for (int kt2 = 0; kt2 < 2; kt2++) {
                int s = kt2 * 2;
                ua[kt2][0] = packh2(u[s][0], u[s][1]);
                ua[kt2][1] = packh2(u[s][2], u[s][3]);
                ua[kt2][2] = packh2(u[s + 1][0], u[s + 1][1]);
                ua[kt2][3] = packh2(u[s + 1][2], u[s + 1][3]);
            }
            float e[4][4];
#pragma unroll
            for (int nt = 0; nt < 4; nt++) { e[nt][0] = e[nt][1] = e[nt][2] = e[nt][3] = 0.f; }
#pragma unroll
            for (int kt2 = 0; kt2 < 2; kt2++)
#pragma unroll
                for (int nt = 0; nt < 4; nt++) {
                    mma16816(e[nt][0], e[nt][1], e[nt][2], e[nt][3],
                             ua[kt2][0], ua[kt2][1], ua[kt2][2], ua[kt2][3],
                             bah[kt2][nt][0], bah[kt2][nt][1]);
                    mma16816(e[nt][0], e[nt][1], e[nt][2], e[nt][3],
                             ua[kt2][0], ua[kt2][1], ua[kt2][2], ua[kt2][3],
                             bal[kt2][nt][0], bal[kt2][nt][1]);
                }
#pragma unroll
            for (int nt = 0; nt < 4; nt++) {
                po[(base + row) * 16 + nt * 4 + (lane & 3)] = packh2(e[nt][0], e[nt][1]);
                po[(base + row + 8) * 16 + nt * 4 + (lane & 3)] = packh2(e[nt][2], e[nt][3]);
            }
        } else {
            float m0 = (base + row < n_nodes) ? 1.0f : 0.0f;
            float m1 = (base + row + 8 < n_nodes) ? 1.0f : 0.0f;
#pragma unroll
            for (int nt = 0; nt < 4; nt++) {
                pacc0[nt] += m0 * u[nt][0] + m1 * u[nt][2];
                pacc1[nt] += m0 * u[nt][1] + m1 * u[nt][3];
            }
        }
    }

    if (LAST) {
#pragma unroll
        for (int nt = 0; nt < 4; nt++) {
            atomicAdd(&ps[nt * 8 + kq], pacc0[nt]);
            atomicAdd(&ps[nt * 8 + kq + 1], pacc1[nt]);
        }
        __syncthreads();
        if (threadIdx.x < DIM) atomicAdd(&g_pool[threadIdx.x], ps[threadIdx.x]);
    }
}

// ---------------- head: consumes g_pool, then RESETS it for next call --------
__global__ void k_head(const float* __restrict__ fcw, const float* __restrict__ fcb,
                       const float* __restrict__ outw, const float* __restrict__ outb,
                       float* __restrict__ out) {
    __shared__ float g2[DIM];
    __shared__ float gp[DIM];
    int j = threadIdx.x;
    float pv = g_pool[j];
    g_pool[j] = 0.0f;
    gp[j] = pv;
    __syncwarp();
    float acc = fcb[j];
    for (int k = 0; k < DIM; k++) acc = fmaf(gp[k], fcw[k * DIM + j], acc);
    g2[j] = fmaxf(acc, 0.0f);
    __syncwarp();
    float o = outb[j];
    for (int k = 0; k < DIM; k++) o = fmaf(g2[k], outw[k * DIM + j], o);
    out[j] = o;
}

// ---------------- launch ------------------------------------------------------
extern "C" void kernel_launch(void* const* d_in, const int* in_sizes, int n_in,
                              void* d_out, int out_size) {
    const float* x    = (const float*)d_in[0];
    const int*   ei   = (const int*)d_in[1];
    const float* w1a  = (const float*)d_in[2];
    const float* b1a  = (const float*)d_in[3];
    const float* w1b  = (const float*)d_in[4];
    const float* b1b  = (const float*)d_in[5];
    const float* wa   = (const float*)d_in[6];
    const float* ba   = (const float*)d_in[7];
    const float* wb   = (const float*)d_in[8];
    const float* bb   = (const float*)d_in[9];
    const float* fcw  = (const float*)d_in[10];
    const float* fcb  = (const float*)d_in[11];
    const float* outw = (const float*)d_in[12];
    const float* outb = (const float*)d_in[13];

    int in_dim  = in_sizes[2] / DIM;
    int n_nodes = in_sizes[0] / in_dim;
    int n_edges = in_sizes[1] / 2;
    const int* src = ei;
    const int* dst = ei + n_edges;

    __half *p0, *p1;
    cudaGetSymbolAddress((void**)&p0, g_p0);
    cudaGetSymbolAddress((void**)&p1, g_p1);

    // CSR build + fused projection
    k_hist<<<1024, 256>>>(dst, n_edges);
    int nb = (n_nodes + SCAN_BLK - 1) / SCAN_BLK;
    k_scan1<<<nb, SCAN_BLK>>>(n_nodes);
    k_scan3<<<256, 256>>>(n_nodes, n_edges, nb);
    k_fillproj<<<PROJ_BLOCKS + FILL_BLOCKS, 256>>>(src, dst, n_edges,
                                                   x, w1a, n_nodes, in_dim);

    // 5 layers: agg (gather) + mlp (tensor-core GEMM chain)
    k_agg<<<2048, 256>>>(p0, b1a, n_nodes);
    k_mlp<false><<<256, 256>>>(p1, w1b, b1b, wa + 0 * DIM * DIM, n_nodes);

    k_agg<<<2048, 256>>>(p1, ba + 0 * DIM, n_nodes);
    k_mlp<false><<<256, 256>>>(p0, wb + 0 * DIM * DIM, bb + 0 * DIM,
                               wa + 1 * DIM * DIM, n_nodes);

    k_agg<<<2048, 256>>>(p0, ba + 1 * DIM, n_nodes);
    k_mlp<false><<<256, 256>>>(p1, wb + 1 * DIM * DIM, bb + 1 * DIM,
                               wa + 2 * DIM * DIM, n_nodes);

    k_agg<<<2048, 256>>>(p1, ba + 2 * DIM, n_nodes);
    k_mlp<false><<<256, 256>>>(p0, wb + 2 * DIM * DIM, bb + 2 * DIM,
                               wa + 3 * DIM * DIM, n_nodes);

    k_agg<<<2048, 256>>>(p0, ba + 3 * DIM, n_nodes);
    k_mlp<true><<<256, 256>>>(p1, wb + 3 * DIM * DIM, bb + 3 * DIM,
                              nullptr, n_nodes);

    // graph head (also resets g_pool)
    k_head<<<1, 32>>>(fcw, fcb, outw, outb, (float*)d_out);
}

// round 14
// speedup vs baseline: 1.8611x; 1.0553x over previous
#include <cuda_runtime.h>
#include <cuda_fp16.h>
#include <cstdint>

#define DIM 32
#define NODES_MAX 100000
#define EDGES_MAX 3200000
#define SCAN_BLK 1024
#define NB_MAX 128   // ceil(100000/1024)=98

#define PROJ_BLOCKS 512
#define FILL_BLOCKS 2048

// ---------------- scratch (device globals; no allocation allowed) ------------
// Invariant at entry: g_deg all-zero, g_pool all-zero (zero at load;
// k_scan1 / k_head restore them every call).
// p buffers padded +16 rows: tile kernels write whole 16-row tiles.
__device__ __half g_p0[(NODES_MAX + 16) * DIM];
__device__ __half g_p1[(NODES_MAX + 16) * DIM];
__device__ __half g_t[(NODES_MAX + 16) * DIM];   // agg output (padded tile)
__device__ int    g_deg[NODES_MAX];
__device__ int    g_row[NODES_MAX + 1];
__device__ int    g_wcur[NODES_MAX];
__device__ int    g_ssrc[EDGES_MAX];
__device__ int    g_bsum[NB_MAX];
__device__ float  g_pool[DIM];

// ---------------- HMMA helpers -----------------------------------------------
__device__ __forceinline__ void mma16816(float& d0, float& d1, float& d2, float& d3,
                                         uint32_t a0, uint32_t a1, uint32_t a2,
                                         uint32_t a3, uint32_t b0, uint32_t b1) {
    asm volatile(
        "mma.sync.aligned.m16n8k16.row.col.f32.f16.f16.f32 "
        "{%0,%1,%2,%3}, {%4,%5,%6,%7}, {%8,%9}, {%0,%1,%2,%3};"
        : "+f"(d0), "+f"(d1), "+f"(d2), "+f"(d3)
        : "r"(a0), "r"(a1), "r"(a2), "r"(a3), "r"(b0), "r"(b1));
}

__device__ __forceinline__ uint32_t packh2(float x, float y) {
    __half2 h = __floats2half2_rn(x, y);
    return *(uint32_t*)&h;
}

// ---------------- CSR build --------------------------------------------------
__global__ void k_hist(const int* __restrict__ dst, int n_edges) {
    int stride = gridDim.x * blockDim.x;
    int gid = blockIdx.x * blockDim.x + threadIdx.x;
    int n4 = n_edges >> 2;
    const int4* d4 = (const int4*)dst;
    for (int i = gid; i < n4; i += stride) {
        int4 v = __ldg(&d4[i]);
        atomicAdd(&g_deg[v.x], 1);
        atomicAdd(&g_deg[v.y], 1);
        atomicAdd(&g_deg[v.z], 1);
        atomicAdd(&g_deg[v.w], 1);
    }
    int base = n4 << 2;
    if (gid < (n_edges - base))
        atomicAdd(&g_deg[__ldg(&dst[base + gid])], 1);
}

__global__ void k_scan1(int n_nodes) {
    __shared__ int s[SCAN_BLK];
    int tid = threadIdx.x;
    int i = blockIdx.x * SCAN_BLK + tid;
    int v = 0;
    if (i < n_nodes) { v = g_deg[i]; g_deg[i] = 0; }
    s[tid] = v;
    __syncthreads();
    for (int off = 1; off < SCAN_BLK; off <<= 1) {
        int t = (tid >= off) ? s[tid - off] : 0;
        __syncthreads();
        s[tid] += t;
        __syncthreads();
    }
    if (i < n_nodes) g_row[i] = s[tid] - v;
    if (tid == SCAN_BLK - 1) g_bsum[blockIdx.x] = s[tid];
}

__global__ void k_scan3(int n_nodes, int n_edges, int nb) {
    __shared__ int sb[NB_MAX];
    __shared__ int sex[NB_MAX];
    int tid = threadIdx.x;
    int v = 0;
    if (tid < NB_MAX) {
        v = (tid < nb) ? g_bsum[tid] : 0;
        sb[tid] = v;
    }
    __syncthreads();
    for (int off = 1; off < NB_MAX; off <<= 1) {
        int t = 0;
        if (tid < NB_MAX && tid >= off) t = sb[tid - off];
        __syncthreads();
        if (tid < NB_MAX) sb[tid] += t;
        __syncthreads();
    }
    if (tid < NB_MAX) sex[tid] = sb[tid] - v;
    __syncthreads();

    int stride = gridDim.x * blockDim.x;
    int gid = blockIdx.x * blockDim.x + tid;
    for (int i = gid; i < n_nodes; i += stride) {
        int r = g_row[i] + sex[i / SCAN_BLK];
        g_row[i] = r;
        g_wcur[i] = r;
    }
    if (gid == 0) g_row[n_nodes] = n_edges;
}

// ---------------- fused fill + HMMA proj -------------------------------------
// Blocks [0, PROJ_BLOCKS): p0 = half(x @ w1a) via m16n8k16 tensor cores
//   (double-half weight splitting; x converted fp32->fp16 on load).
// Blocks [PROJ_BLOCKS, +FILL_BLOCKS): CSR fill (int4 edge reads).
__global__ void __launch_bounds__(256)
k_fillproj(const int* __restrict__ src, const int* __restrict__ dst, int n_edges,
           const float* __restrict__ x, const float* __restrict__ w1a,
           int n_nodes, int in_dim) {
    if (blockIdx.x < PROJ_BLOCKS) {
        // ---- tensor-core projection path ----
        int lane = threadIdx.x & 31;
        int bcol = lane >> 2;
        int kq   = (lane & 3) * 2;
        int row  = lane >> 2;

        // B fragments for w1a [in_dim, 32]; K padded to 80 (5 k-tiles).
        uint32_t bh[5][4][2], bl[5][4][2];
#pragma unroll
        for (int kt = 0; kt < 5; kt++)
#pragma unroll
            for (int nt = 0; nt < 4; nt++)
#pragma unroll
                for (int rr = 0; rr < 2; rr++) {
                    int k0 = kt * 16 + kq + rr * 8;
                    int j = nt * 8 + bcol;
                    float w0 = (k0 < in_dim) ? __ldg(&w1a[k0 * DIM + j]) : 0.0f;
                    float w1 = (k0 + 1 < in_dim) ? __ldg(&w1a[(k0 + 1) * DIM + j]) : 0.0f;
                    __half2 h = __floats2half2_rn(w0, w1);
                    bh[kt][nt][rr] = *(uint32_t*)&h;
                    bl[kt][nt][rr] = packh2(w0 - __low2float(h), w1 - __high2float(h));
                }

        const float2* __restrict__ x2 = (const float2*)x;
        int ld2 = in_dim >> 1;            // float2 per row (in_dim even)
        uint32_t* __restrict__ po = (uint32_t*)g_p0;

        int warp = (blockIdx.x * blockDim.x + threadIdx.x) >> 5;
        int nwarp = (PROJ_BLOCKS * blockDim.x) >> 5;
        int n_tiles = (n_nodes + 15) >> 4;

        for (int tile = warp; tile < n_tiles; tile += nwarp) {
            int base = tile * 16;
            int rA = min(base + row, n_nodes - 1);
            int rB = min(base + row + 8, n_nodes - 1);

            float d[4][4];
#pragma unroll
            for (int nt = 0; nt < 4; nt++) { d[nt][0] = d[nt][1] = d[nt][2] = d[nt][3] = 0.f; }

#pragma unroll
            for (int kt = 0; kt < 5; kt++) {
                int i0 = kt * 8 + (lane & 3);      // float2 col index (cols 2*i0, 2*i0+1)
                float2 fz = make_float2(0.f, 0.f);
                float2 f0 = (2 * i0 < in_dim) ? __ldg(&x2[(size_t)rA * ld2 + i0]) : fz;
                float2 f1 = (2 * i0 < in_dim) ? __ldg(&x2[(size_t)rB * ld2 + i0]) : fz;
                float2 f2 = (2 * (i0 + 4) < in_dim) ? __ldg(&x2[(size_t)rA * ld2 + i0 + 4]) : fz;
                float2 f3 = (2 * (i0 + 4) < in_dim) ? __ldg(&x2[(size_t)rB * ld2 + i0 + 4]) : fz;
                uint32_t a0 = packh2(f0.x, f0.y);
                uint32_t a1 = packh2(f1.x, f1.y);
                uint32_t a2 = packh2(f2.x, f2.y);
                uint32_t a3 = packh2(f3.x, f3.y);
#pragma unroll
                for (int nt = 0; nt < 4; nt++) {
                    mma16816(d[nt][0], d[nt][1], d[nt][2], d[nt][3],
                             a0, a1, a2, a3, bh[kt][nt][0], bh[kt][nt][1]);
                    mma16816(d[nt][0], d[nt][1], d[nt][2], d[nt][3],
                             a0, a1, a2, a3, bl[kt][nt][0], bl[kt][nt][1]);
                }
            }
#pragma unroll
            for (int nt = 0; nt < 4; nt++) {
                po[(base + row) * 16 + nt * 4 + (lane & 3)] = packh2(d[nt][0], d[nt][1]);
                po[(base + row + 8) * 16 + nt * 4 + (lane & 3)] = packh2(d[nt][2], d[nt][3]);
            }
        }
    } else {
        // ---- CSR fill path (int4 vectorized) ----
        int gid = (blockIdx.x - PROJ_BLOCKS) * blockDim.x + threadIdx.x;
        int stride = FILL_BLOCKS * blockDim.x;
        int n4 = n_edges >> 2;
        const int4* s4 = (const int4*)src;
        const int4* d4 = (const int4*)dst;
        for (int i = gid; i < n4; i += stride) {
            int4 d = __ldg(&d4[i]);
            int4 s = __ldg(&s4[i]);
            g_ssrc[atomicAdd(&g_wcur[d.x], 1)] = s.x;
            g_ssrc[atomicAdd(&g_wcur[d.y], 1)] = s.y;
            g_ssrc[atomicAdd(&g_wcur[d.z], 1)] = s.z;
            g_ssrc[atomicAdd(&g_wcur[d.w], 1)] = s.w;
        }
        int base = n4 << 2;
        if (gid < (n_edges - base)) {
            int i = base + gid;
            g_ssrc[atomicAdd(&g_wcur[__ldg(&dst[i])], 1)] = __ldg(&src[i]);
        }
    }
}

// ---------------- aggregation: t[n] = relu(sum_src p[src] + p[n] + Ba) -------
__global__ void __launch_bounds__(256)
k_agg(const __half* __restrict__ p_in, const float* __restrict__ Bav, int n_nodes) {
    const __half2* __restrict__ p2 = (const __half2*)p_in;
    __half2* __restrict__ t2 = (__half2*)g_t;
    int lane = threadIdx.x & 31;
    int half_id = lane >> 4;
    int fl = lane & 15;
    float ba_x = Bav[2 * fl], ba_y = Bav[2 * fl + 1];

    int warp = (blockIdx.x * blockDim.x + threadIdx.x) >> 5;
    int nwarp = (gridDim.x * blockDim.x) >> 5;

    for (int n = warp; n < n_nodes; n += nwarp) {
        int beg = g_row[n];
        int end = g_row[n + 1];

        float ax0 = 0.f, ay0 = 0.f, ax1 = 0.f, ay1 = 0.f;
        float ax2 = 0.f, ay2 = 0.f, ax3 = 0.f, ay3 = 0.f;
        float ax4 = 0.f, ay4 = 0.f, ax5 = 0.f, ay5 = 0.f;
        float ax6 = 0.f, ay6 = 0.f, ax7 = 0.f, ay7 = 0.f;
        int e = beg;
        for (; e + 16 <= end; e += 16) {
            int s0 = g_ssrc[e + 0 + half_id];
            int s1 = g_ssrc[e + 2 + half_id];
            int s2 = g_ssrc[e + 4 + half_id];
            int s3 = g_ssrc[e + 6 + half_id];
            int s4 = g_ssrc[e + 8 + half_id];
            int s5 = g_ssrc[e + 10 + half_id];
            int s6 = g_ssrc[e + 12 + half_id];
            int s7 = g_ssrc[e + 14 + half_id];
            float2 f0 = __half22float2(p2[s0 * 16 + fl]);
            float2 f1 = __half22float2(p2[s1 * 16 + fl]);
            float2 f2 = __half22float2(p2[s2 * 16 + fl]);
            float2 f3 = __half22float2(p2[s3 * 16 + fl]);
            float2 f4 = __half22float2(p2[s4 * 16 + fl]);
            float2 f5 = __half22float2(p2[s5 * 16 + fl]);
            float2 f6 = __half22float2(p2[s6 * 16 + fl]);
            float2 f7 = __half22float2(p2[s7 * 16 + fl]);
            ax0 += f0.x; ay0 += f0.y;
            ax1 += f1.x; ay1 += f1.y;
            ax2 += f2.x; ay2 += f2.y;
            ax3 += f3.x; ay3 += f3.y;
            ax4 += f4.x; ay4 += f4.y;
            ax5 += f5.x; ay5 += f5.y;
            ax6 += f6.x; ay6 += f6.y;
            ax7 += f7.x; ay7 += f7.y;
        }
        for (; e + 2 <= end; e += 2) {
            int s = g_ssrc[e + half_id];
            float2 f = __half22float2(p2[s * 16 + fl]);
            ax0 += f.x; ay0 += f.y;
        }
        if (e < end && half_id == 0) {
            int s = g_ssrc[e];
            float2 f = __half22float2(p2[s * 16 + fl]);
            ax0 += f.x; ay0 += f.y;
        }

        float tx = ((ax0 + ax1) + (ax2 + ax3)) + ((ax4 + ax5) + (ax6 + ax7));
        float ty = ((ay0 + ay1) + (ay2 + ay3)) + ((ay4 + ay5) + (ay6 + ay7));
        tx += __shfl_xor_sync(0xffffffffu, tx, 16);
        ty += __shfl_xor_sync(0xffffffffu, ty, 16);
        float2 sv = __half22float2(p2[n * 16 + fl]);
        tx = fmaxf(tx + sv.x + ba_x, 0.0f);
        ty = fmaxf(ty + sv.y + ba_y, 0.0f);

        if (half_id == 0) t2[n * 16 + fl] = __floats2half2_rn(tx, ty);
    }
}

// ---------------- MLP via HMMA: p_out = relu(t@Wb+Bb) @ Wa -------------------
template <bool LAST>
__global__ void __launch_bounds__(256)
k_mlp(__half* __restrict__ p_out, const float* __restrict__ Wb,
      const float* __restrict__ Bb, const float* __restrict__ Wa, int n_nodes) {
    int lane = threadIdx.x & 31;
    int bcol = lane >> 2;
    int kq   = (lane & 3) * 2;
    int row  = lane >> 2;

    uint32_t bbh[2][4][2], bbl[2][4][2];
    uint32_t bah[2][4][2], bal[2][4][2];
#pragma unroll
    for (int kt = 0; kt < 2; kt++)
#pragma unroll
        for (int nt = 0; nt < 4; nt++)
#pragma unroll
            for (int rr = 0; rr < 2; rr++) {
                int k0 = kt * 16 + kq + rr * 8;
                int j = nt * 8 + bcol;
                float w0 = __ldg(&Wb[k0 * DIM + j]);
                float w1 = __ldg(&Wb[(k0 + 1) * DIM + j]);
                __half2 h = __floats2half2_rn(w0, w1);
                bbh[kt][nt][rr] = *(uint32_t*)&h;
                bbl[kt][nt][rr] = packh2(w0 - __low2float(h), w1 - __high2float(h));
                if (!LAST) {
                    float v0 = __ldg(&Wa[k0 * DIM + j]);
                    float v1 = __ldg(&Wa[(k0 + 1) * DIM + j]);
                    __half2 g = __floats2half2_rn(v0, v1);
                    bah[kt][nt][rr] = *(uint32_t*)&g;
                    bal[kt][nt][rr] = packh2(v0 - __low2float(g), v1 - __high2float(g));
                }
            }
    float bb0[4], bb1[4];
#pragma unroll
    for (int nt = 0; nt < 4; nt++) {
        bb0[nt] = __ldg(&Bb[nt * 8 + kq]);
        bb1[nt] = __ldg(&Bb[nt * 8 + kq + 1]);
    }

    float pacc0[4] = {0, 0, 0, 0}, pacc1[4] = {0, 0, 0, 0};
    __shared__ float ps[DIM];
    if (LAST) {
        if (threadIdx.x < DIM) ps[threadIdx.x] = 0.0f;
        __syncthreads();
    }

    const uint32_t* __restrict__ t32 = (const uint32_t*)g_t;
    uint32_t* __restrict__ po = (uint32_t*)p_out;

    int warp = (blockIdx.x * blockDim.x + threadIdx.x) >> 5;
    int nwarp = (gridDim.x * blockDim.x) >> 5;
    int n_tiles = (n_nodes + 15) >> 4;

    for (int tile = warp; tile < n_tiles; tile += nwarp) {
        int base = tile * 16;
        uint32_t a[2][4];
#pragma unroll
        for (int kt = 0; kt < 2; kt++) {
            int o = kt * 8 + (lane & 3);
            a[kt][0] = t32[(base + row) * 16 + o];
            a[kt][1] = t32[(base + row + 8) * 16 + o];
            a[kt][2] = t32[(base + row) * 16 + o + 4];
            a[kt][3] = t32[(base + row + 8) * 16 + o + 4];
        }

        float d[4][4];
#pragma unroll
        for (int nt = 0; nt < 4; nt++) { d[nt][0] = d[nt][1] = d[nt][2] = d[nt][3] = 0.f; }
#pragma unroll
        for (int kt = 0; kt < 2; kt++)
#pragma unroll
            for (int nt = 0; nt < 4; nt++) {
                mma16816(d[nt][0], d[nt][1], d[nt][2], d[nt][3],
                         a[kt][0], a[kt][1], a[kt][2], a[kt][3],
                         bbh[kt][nt][0], bbh[kt][nt][1]);
                mma16816(d[nt][0], d[nt][1], d[nt][2], d[nt][3],
                         a[kt][0], a[kt][1], a[kt][2], a[kt][3],
                         bbl[kt][nt][0], bbl[kt][nt][1]);
            }
        float u[4][4];
#pragma unroll
        for (int nt = 0; nt < 4; nt++) {
            u[nt][0] = fmaxf(d[nt][0] + bb0[nt], 0.f);
            u[nt][1] = fmaxf(d[nt][1] + bb1[nt], 0.f);
            u[nt][2] = fmaxf(d[nt][2] + bb0[nt], 0.f);
            u[nt][3] = fmaxf(d[nt][3] + bb1[nt], 0.f);
        }

        if (!LAST) {
            uint32_t ua[2][4];
#pragma unroll
            for (int kt2 = 0; kt2 < 2; kt2++) {
                int s = kt2 * 2;
                ua[kt2][0] = packh2(u[s][0], u[s][1]);
                ua[kt2][1] = packh2(u[s][2], u[s][3]);
                ua[kt2][2] = packh2(u[s + 1][0], u[s + 1][1]);
                ua[kt2][3] = packh2(u[s + 1][2], u[s + 1][3]);
            }
            float e[4][4];
#pragma unroll
            for (int nt = 0; nt < 4; nt++) { e[nt][0] = e[nt][1] = e[nt][2] = e[nt][3] = 0.f; }
#pragma unroll
            for (int kt2 = 0; kt2 < 2; kt2++)
#pragma unroll
                for (int nt = 0; nt < 4; nt++) {
                    mma16816(e[nt][0], e[nt][1], e[nt][2], e[nt][3],
                             ua[kt2][0], ua[kt2][1], ua[kt2][2], ua[kt2][3],
                             bah[kt2][nt][0], bah[kt2][nt][1]);
                    mma16816(e[nt][0], e[nt][1], e[nt][2], e[nt][3],
                             ua[kt2][0], ua[kt2][1], ua[kt2][2], ua[kt2][3],
                             bal[kt2][nt][0], bal[kt2][nt][1]);
                }
#pragma unroll
            for (int nt = 0; nt < 4; nt++) {
                po[(base + row) * 16 + nt * 4 + (lane & 3)] = packh2(e[nt][0], e[nt][1]);
                po[(base + row + 8) * 16 + nt * 4 + (lane & 3)] = packh2(e[nt][2], e[nt][3]);
            }
        } else {
            float m0 = (base + row < n_nodes) ? 1.0f : 0.0f;
            float m1 = (base + row + 8 < n_nodes) ? 1.0f : 0.0f;
#pragma unroll
            for (int nt = 0; nt < 4; nt++) {
                pacc0[nt] += m0 * u[nt][0] + m1 * u[nt][2];
                pacc1[nt] += m0 * u[nt][1] + m1 * u[nt][3];
            }
        }
    }

    if (LAST) {
#pragma unroll
        for (int nt = 0; nt < 4; nt++) {
            atomicAdd(&ps[nt * 8 + kq], pacc0[nt]);
            atomicAdd(&ps[nt * 8 + kq + 1], pacc1[nt]);
        }
        __syncthreads();
        if (threadIdx.x < DIM) atomicAdd(&g_pool[threadIdx.x], ps[threadIdx.x]);
    }
}

// ---------------- head: consumes g_pool, then RESETS it for next call --------
__global__ void k_head(const float* __restrict__ fcw, const float* __restrict__ fcb,
                       const float* __restrict__ outw, const float* __restrict__ outb,
                       float* __restrict__ out) {
    __shared__ float g2[DIM];
    __shared__ float gp[DIM];
    int j = threadIdx.x;
    float pv = g_pool[j];
    g_pool[j] = 0.0f;
    gp[j] = pv;
    __syncwarp();
    float acc = fcb[j];
    for (int k = 0; k < DIM; k++) acc = fmaf(gp[k], fcw[k * DIM + j], acc);
    g2[j] = fmaxf(acc, 0.0f);
    __syncwarp();
    float o = outb[j];
    for (int k = 0; k < DIM; k++) o = fmaf(g2[k], outw[k * DIM + j], o);
    out[j] = o;
}

// ---------------- launch ------------------------------------------------------
extern "C" void kernel_launch(void* const* d_in, const int* in_sizes, int n_in,
                              void* d_out, int out_size) {
    const float* x    = (const float*)d_in[0];
    const int*   ei   = (const int*)d_in[1];
    const float* w1a  = (const float*)d_in[2];
    const float* b1a  = (const float*)d_in[3];
    const float* w1b  = (const float*)d_in[4];
    const float* b1b  = (const float*)d_in[5];
    const float* wa   = (const float*)d_in[6];
    const float* ba   = (const float*)d_in[7];
    const float* wb   = (const float*)d_in[8];
    const float* bb   = (const float*)d_in[9];
    const float* fcw  = (const float*)d_in[10];
    const float* fcb  = (const float*)d_in[11];
    const float* outw = (const float*)d_in[12];
    const float* outb = (const float*)d_in[13];

    int in_dim  = in_sizes[2] / DIM;
    int n_nodes = in_sizes[0] / in_dim;
    int n_edges = in_sizes[1] / 2;
    const int* src = ei;
    const int* dst = ei + n_edges;

    __half *p0, *p1;
    cudaGetSymbolAddress((void**)&p0, g_p0);
    cudaGetSymbolAddress((void**)&p1, g_p1);

    // CSR build + fused tensor-core projection
    k_hist<<<1024, 256>>>(dst, n_edges);
    int nb = (n_nodes + SCAN_BLK - 1) / SCAN_BLK;
    k_scan1<<<nb, SCAN_BLK>>>(n_nodes);
    k_scan3<<<256, 256>>>(n_nodes, n_edges, nb);
    k_fillproj<<<PROJ_BLOCKS + FILL_BLOCKS, 256>>>(src, dst, n_edges,
                                                   x, w1a, n_nodes, in_dim);

    // 5 layers: agg (gather) + mlp (tensor-core GEMM chain)
    k_agg<<<2048, 256>>>(p0, b1a, n_nodes);
    k_mlp<false><<<256, 256>>>(p1, w1b, b1b, wa + 0 * DIM * DIM, n_nodes);

    k_agg<<<2048, 256>>>(p1, ba + 0 * DIM, n_nodes);
    k_mlp<false><<<256, 256>>>(p0, wb + 0 * DIM * DIM, bb + 0 * DIM,
                               wa + 1 * DIM * DIM, n_nodes);

    k_agg<<<2048, 256>>>(p0, ba + 1 * DIM, n_nodes);
    k_mlp<false><<<256, 256>>>(p1, wb + 1 * DIM * DIM, bb + 1 * DIM,
                               wa + 2 * DIM * DIM, n_nodes);

    k_agg<<<2048, 256>>>(p1, ba + 2 * DIM, n_nodes);
    k_mlp<false><<<256, 256>>>(p0, wb + 2 * DIM * DIM, bb + 2 * DIM,
                               wa + 3 * DIM * DIM, n_nodes);

    k_agg<<<2048, 256>>>(p0, ba + 3 * DIM, n_nodes);
    k_mlp<true><<<256, 256>>>(p1, wb + 3 * DIM * DIM, bb + 3 * DIM,
                              nullptr, n_nodes);

    // graph head (also resets g_pool)
    k_head<<<1, 32>>>(fcw, fcb, outw, outb, (float*)d_out);
}

// round 15
// speedup vs baseline: 1.9112x; 1.0269x over previous
#include <cuda_runtime.h>
#include <cuda_fp16.h>
#include <cstdint>

#define DIM 32
#define NODES_MAX 100000
#define EDGES_MAX 3200000
#define SCAN_BLK 1024
#define NB_MAX 128   // ceil(100000/1024)=98

// ---------------- scratch (device globals; no allocation allowed) ------------
// Invariant at entry: g_deg all-zero, g_pool all-zero (zero at load;
// k_scan1 / k_head restore them every call).
// p buffers padded +16 rows: tile kernels write whole 16-row tiles.
__device__ __half g_p0[(NODES_MAX + 16) * DIM];
__device__ __half g_p1[(NODES_MAX + 16) * DIM];
__device__ __half g_t[(NODES_MAX + 16) * DIM];   // agg output (padded tile)
__device__ int    g_deg[NODES_MAX];
__device__ int    g_row[NODES_MAX + 1];
__device__ int    g_wcur[NODES_MAX];
__device__ int    g_ssrc[EDGES_MAX];
__device__ int    g_bsum[NB_MAX];
__device__ float  g_pool[DIM];

// ---------------- HMMA helpers -----------------------------------------------
__device__ __forceinline__ void mma16816(float& d0, float& d1, float& d2, float& d3,
                                         uint32_t a0, uint32_t a1, uint32_t a2,
                                         uint32_t a3, uint32_t b0, uint32_t b1) {
    asm volatile(
        "mma.sync.aligned.m16n8k16.row.col.f32.f16.f16.f32 "
        "{%0,%1,%2,%3}, {%4,%5,%6,%7}, {%8,%9}, {%0,%1,%2,%3};"
        : "+f"(d0), "+f"(d1), "+f"(d2), "+f"(d3)
        : "r"(a0), "r"(a1), "r"(a2), "r"(a3), "r"(b0), "r"(b1));
}

__device__ __forceinline__ uint32_t packh2(float x, float y) {
    __half2 h = __floats2half2_rn(x, y);
    return *(uint32_t*)&h;
}

// ---------------- CSR build --------------------------------------------------
__global__ void k_hist(const int* __restrict__ dst, int n_edges) {
    int stride = gridDim.x * blockDim.x;
    int gid = blockIdx.x * blockDim.x + threadIdx.x;
    int n4 = n_edges >> 2;
    const int4* d4 = (const int4*)dst;
    for (int i = gid; i < n4; i += stride) {
        int4 v = __ldg(&d4[i]);
        atomicAdd(&g_deg[v.x], 1);
        atomicAdd(&g_deg[v.y], 1);
        atomicAdd(&g_deg[v.z], 1);
        atomicAdd(&g_deg[v.w], 1);
    }
    int base = n4 << 2;
    if (gid < (n_edges - base))
        atomicAdd(&g_deg[__ldg(&dst[base + gid])], 1);
}

__global__ void k_scan1(int n_nodes) {
    __shared__ int s[SCAN_BLK];
    int tid = threadIdx.x;
    int i = blockIdx.x * SCAN_BLK + tid;
    int v = 0;
    if (i < n_nodes) { v = g_deg[i]; g_deg[i] = 0; }
    s[tid] = v;
    __syncthreads();
    for (int off = 1; off < SCAN_BLK; off <<= 1) {
        int t = (tid >= off) ? s[tid - off] : 0;
        __syncthreads();
        s[tid] += t;
        __syncthreads();
    }
    if (i < n_nodes) g_row[i] = s[tid] - v;
    if (tid == SCAN_BLK - 1) g_bsum[blockIdx.x] = s[tid];
}

__global__ void k_scan3(int n_nodes, int n_edges, int nb) {
    __shared__ int sb[NB_MAX];
    __shared__ int sex[NB_MAX];
    int tid = threadIdx.x;
    int v = 0;
    if (tid < NB_MAX) {
        v = (tid < nb) ? g_bsum[tid] : 0;
        sb[tid] = v;
    }
    __syncthreads();
    for (int off = 1; off < NB_MAX; off <<= 1) {
        int t = 0;
        if (tid < NB_MAX && tid >= off) t = sb[tid - off];
        __syncthreads();
        if (tid < NB_MAX) sb[tid] += t;
        __syncthreads();
    }
    if (tid < NB_MAX) sex[tid] = sb[tid] - v;
    __syncthreads();

    int stride = gridDim.x * blockDim.x;
    int gid = blockIdx.x * blockDim.x + tid;
    for (int i = gid; i < n_nodes; i += stride) {
        int r = g_row[i] + sex[i / SCAN_BLK];
        g_row[i] = r;
        g_wcur[i] = r;
    }
    if (gid == 0) g_row[n_nodes] = n_edges;
}

__global__ void k_fill(const int* __restrict__ src, const int* __restrict__ dst,
                       int n_edges) {
    int gid = blockIdx.x * blockDim.x + threadIdx.x;
    int stride = gridDim.x * blockDim.x;
    int n4 = n_edges >> 2;
    const int4* s4 = (const int4*)src;
    const int4* d4 = (const int4*)dst;
    for (int i = gid; i < n4; i += stride) {
        int4 d = __ldg(&d4[i]);
        int4 s = __ldg(&s4[i]);
        g_ssrc[atomicAdd(&g_wcur[d.x], 1)] = s.x;
        g_ssrc[atomicAdd(&g_wcur[d.y], 1)] = s.y;
        g_ssrc[atomicAdd(&g_wcur[d.z], 1)] = s.z;
        g_ssrc[atomicAdd(&g_wcur[d.w], 1)] = s.w;
    }
    int base = n4 << 2;
    if (gid < (n_edges - base)) {
        int i = base + gid;
        g_ssrc[atomicAdd(&g_wcur[__ldg(&dst[i])], 1)] = __ldg(&src[i]);
    }
}

// ---------------- projection via HMMA: p0 = half(x @ w1a) --------------------
// m16n8k16 tensor cores, double-half weight splitting; 16-node tiles.
__global__ void __launch_bounds__(256)
k_proj(const float* __restrict__ x, const float* __restrict__ w1a,
       int n_nodes, int in_dim) {
    int lane = threadIdx.x & 31;
    int bcol = lane >> 2;
    int kq   = (lane & 3) * 2;
    int row  = lane >> 2;

    // B fragments for w1a [in_dim, 32]; K padded to 80 (5 k-tiles).
    uint32_t bh[5][4][2], bl[5][4][2];
#pragma unroll
    for (int kt = 0; kt < 5; kt++)
#pragma unroll
        for (int nt = 0; nt < 4; nt++)
#pragma unroll
            for (int rr = 0; rr < 2; rr++) {
                int k0 = kt * 16 + kq + rr * 8;
                int j = nt * 8 + bcol;
                float w0 = (k0 < in_dim) ? __ldg(&w1a[k0 * DIM + j]) : 0.0f;
                float w1 = (k0 + 1 < in_dim) ? __ldg(&w1a[(k0 + 1) * DIM + j]) : 0.0f;
                __half2 h = __floats2half2_rn(w0, w1);
                bh[kt][nt][rr] = *(uint32_t*)&h;
                bl[kt][nt][rr] = packh2(w0 - __low2float(h), w1 - __high2float(h));
            }

    const float2* __restrict__ x2 = (const float2*)x;
    int ld2 = in_dim >> 1;            // float2 per row (in_dim even)
    uint32_t* __restrict__ po = (uint32_t*)g_p0;

    int warp = (blockIdx.x * blockDim.x + threadIdx.x) >> 5;
    int nwarp = (gridDim.x * blockDim.x) >> 5;
    int n_tiles = (n_nodes + 15) >> 4;

    for (int tile = warp; tile < n_tiles; tile += nwarp) {
        int base = tile * 16;
        int rA = min(base + row, n_nodes - 1);
        int rB = min(base + row + 8, n_nodes - 1);

        float d[4][4];
#pragma unroll
        for (int nt = 0; nt < 4; nt++) { d[nt][0] = d[nt][1] = d[nt][2] = d[nt][3] = 0.f; }

#pragma unroll
        for (int kt = 0; kt < 5; kt++) {
            int i0 = kt * 8 + (lane & 3);      // float2 col index (cols 2*i0, 2*i0+1)
            float2 fz = make_float2(0.f, 0.f);
            float2 f0 = (2 * i0 < in_dim) ? __ldg(&x2[(size_t)rA * ld2 + i0]) : fz;
            float2 f1 = (2 * i0 < in_dim) ? __ldg(&x2[(size_t)rB * ld2 + i0]) : fz;
            float2 f2 = (2 * (i0 + 4) < in_dim) ? __ldg(&x2[(size_t)rA * ld2 + i0 + 4]) : fz;
            float2 f3 = (2 * (i0 + 4) < in_dim) ? __ldg(&x2[(size_t)rB * ld2 + i0 + 4]) : fz;
            uint32_t a0 = packh2(f0.x, f0.y);
            uint32_t a1 = packh2(f1.x, f1.y);
            uint32_t a2 = packh2(f2.x, f2.y);
            uint32_t a3 = packh2(f3.x, f3.y);
#pragma unroll
            for (int nt = 0; nt < 4; nt++) {
                mma16816(d[nt][0], d[nt][1], d[nt][2], d[nt][3],
                         a0, a1, a2, a3, bh[kt][nt][0], bh[kt][nt][1]);
                mma16816(d[nt][0], d[nt][1], d[nt][2], d[nt][3],
                         a0, a1, a2, a3, bl[kt][nt][0], bl[kt][nt][1]);
            }
        }
#pragma unroll
        for (int nt = 0; nt < 4; nt++) {
            po[(base + row) * 16 + nt * 4 + (lane & 3)] = packh2(d[nt][0], d[nt][1]);
            po[(base + row + 8) * 16 + nt * 4 + (lane & 3)] = packh2(d[nt][2], d[nt][3]);
        }
    }
}

// ---------------- aggregation: t[n] = relu(sum_src p[src] + p[n] + Ba) -------
__global__ void __launch_bounds__(256)
k_agg(const __half* __restrict__ p_in, const float* __restrict__ Bav, int n_nodes) {
    const __half2* __restrict__ p2 = (const __half2*)p_in;
    __half2* __restrict__ t2 = (__half2*)g_t;
    int lane = threadIdx.x & 31;
    int half_id = lane >> 4;
    int fl = lane & 15;
    float ba_x = Bav[2 * fl], ba_y = Bav[2 * fl + 1];

    int warp = (blockIdx.x * blockDim.x + threadIdx.x) >> 5;
    int nwarp = (gridDim.x * blockDim.x) >> 5;

    for (int n = warp; n < n_nodes; n += nwarp) {
        int beg = g_row[n];
        int end = g_row[n + 1];

        float ax0 = 0.f, ay0 = 0.f, ax1 = 0.f, ay1 = 0.f;
        float ax2 = 0.f, ay2 = 0.f, ax3 = 0.f, ay3 = 0.f;
        float ax4 = 0.f, ay4 = 0.f, ax5 = 0.f, ay5 = 0.f;
        float ax6 = 0.f, ay6 = 0.f, ax7 = 0.f, ay7 = 0.f;
        int e = beg;
        for (; e + 16 <= end; e += 16) {
            int s0 = g_ssrc[e + 0 + half_id];
            int s1 = g_ssrc[e + 2 + half_id];
            int s2 = g_ssrc[e + 4 + half_id];
            int s3 = g_ssrc[e + 6 + half_id];
            int s4 = g_ssrc[e + 8 + half_id];
            int s5 = g_ssrc[e + 10 + half_id];
            int s6 = g_ssrc[e + 12 + half_id];
            int s7 = g_ssrc[e + 14 + half_id];
            float2 f0 = __half22float2(p2[s0 * 16 + fl]);
            float2 f1 = __half22float2(p2[s1 * 16 + fl]);
            float2 f2 = __half22float2(p2[s2 * 16 + fl]);
            float2 f3 = __half22float2(p2[s3 * 16 + fl]);
            float2 f4 = __half22float2(p2[s4 * 16 + fl]);
            float2 f5 = __half22float2(p2[s5 * 16 + fl]);
            float2 f6 = __half22float2(p2[s6 * 16 + fl]);
            float2 f7 = __half22float2(p2[s7 * 16 + fl]);
            ax0 += f0.x; ay0 += f0.y;
            ax1 += f1.x; ay1 += f1.y;
            ax2 += f2.x; ay2 += f2.y;
            ax3 += f3.x; ay3 += f3.y;
            ax4 += f4.x; ay4 += f4.y;
            ax5 += f5.x; ay5 += f5.y;
            ax6 += f6.x; ay6 += f6.y;
            ax7 += f7.x; ay7 += f7.y;
        }
        for (; e + 2 <= end; e += 2) {
            int s = g_ssrc[e + half_id];
            float2 f = __half22float2(p2[s * 16 + fl]);
            ax0 += f.x; ay0 += f.y;
        }
        if (e < end && half_id == 0) {
            int s = g_ssrc[e];
            float2 f = __half22float2(p2[s * 16 + fl]);
            ax0 += f.x; ay0 += f.y;
        }

        float tx = ((ax0 + ax1) + (ax2 + ax3)) + ((ax4 + ax5) + (ax6 + ax7));
        float ty = ((ay0 + ay1) + (ay2 + ay3)) + ((ay4 + ay5) + (ay6 + ay7));
        tx += __shfl_xor_sync(0xffffffffu, tx, 16);
        ty += __shfl_xor_sync(0xffffffffu, ty, 16);
        float2 sv = __half22float2(p2[n * 16 + fl]);
        tx = fmaxf(tx + sv.x + ba_x, 0.0f);
        ty = fmaxf(ty + sv.y + ba_y, 0.0f);

        if (half_id == 0) t2[n * 16 + fl] = __floats2half2_rn(tx, ty);
    }
}

// ---------------- MLP via HMMA: p_out = relu(t@Wb+Bb) @ Wa -------------------
template <bool LAST>
__global__ void __launch_bounds__(256)
k_mlp(__half* __restrict__ p_out, const float* __restrict__ Wb,
      const float* __restrict__ Bb, const float* __restrict__ Wa, int n_nodes) {
    int lane = threadIdx.x & 31;
    int bcol = lane >> 2;
    int kq   = (lane & 3) * 2;
    int row  = lane >> 2;

    uint32_t bbh[2][4][2], bbl[2][4][2];
    uint32_t bah[2][4][2], bal[2][4][2];
#pragma unroll
    for (int kt = 0; kt < 2; kt++)
#pragma unroll
        for (int nt = 0; nt < 4; nt++)
#pragma unroll
            for (int rr = 0; rr < 2; rr++) {
                int k0 = kt * 16 + kq + rr * 8;
                int j = nt * 8 + bcol;
                float w0 = __ldg(&Wb[k0 * DIM + j]);
                float w1 = __ldg(&Wb[(k0 + 1) * DIM + j]);
                __half2 h = __floats2half2_rn(w0, w1);
                bbh[kt][nt][rr] = *(uint32_t*)&h;
                bbl[kt][nt][rr] = packh2(w0 - __low2float(h), w1 - __high2float(h));
                if (!LAST) {
                    float v0 = __ldg(&Wa[k0 * DIM + j]);
                    float v1 = __ldg(&Wa[(k0 + 1) * DIM + j]);
                    __half2 g = __floats2half2_rn(v0, v1);
                    bah[kt][nt][rr] = *(uint32_t*)&g;
                    bal[kt][nt][rr] = packh2(v0 - __low2float(g), v1 - __high2float(g));
                }
            }
    float bb0[4], bb1[4];
#pragma unroll
    for (int nt = 0; nt < 4; nt++) {
        bb0[nt] = __ldg(&Bb[nt * 8 + kq]);
        bb1[nt] = __ldg(&Bb[nt * 8 + kq + 1]);
    }

    float pacc0[4] = {0, 0, 0, 0}, pacc1[4] = {0, 0, 0, 0};
    __shared__ float ps[DIM];
    if (LAST) {
        if (threadIdx.x < DIM) ps[threadIdx.x] = 0.0f;
        __syncthreads();
    }

    const uint32_t* __restrict__ t32 = (const uint32_t*)g_t;
    uint32_t* __restrict__ po = (uint32_t*)p_out;

    int warp = (blockIdx.x * blockDim.x + threadIdx.x) >> 5;
    int nwarp = (gridDim.x * blockDim.x) >> 5;
    int n_tiles = (n_nodes + 15) >> 4;

    for (int tile = warp; tile < n_tiles; tile += nwarp) {
        int base = tile * 16;
        uint32_t a[2][4];
#pragma unroll
        for (int kt = 0; kt < 2; kt++) {
            int o = kt * 8 + (lane & 3);
            a[kt][0] = t32[(base + row) * 16 + o];
            a[kt][1] = t32[(base + row + 8) * 16 + o];
            a[kt][2] = t32[(base + row) * 16 + o + 4];
            a[kt][3] = t32[(base + row + 8) * 16 + o + 4];
        }

        float d[4][4];
#pragma unroll
        for (int nt = 0; nt < 4; nt++) { d[nt][0] = d[nt][1] = d[nt][2] = d[nt][3] = 0.f; }
#pragma unroll
        for (int kt = 0; kt < 2; kt++)
#pragma unroll
            for (int nt = 0; nt < 4; nt++) {
                mma16816(d[nt][0], d[nt][1], d[nt][2], d[nt][3],
                         a[kt][0], a[kt][1], a[kt][2], a[kt][3],
                         bbh[kt][nt][0], bbh[kt][nt][1]);
                mma16816(d[nt][0], d[nt][1], d[nt][2], d[nt][3],
                         a[kt][0], a[kt][1], a[kt][2], a[kt][3],
                         bbl[kt][nt][0], bbl[kt][nt][1]);
            }
        float u[4][4];
#pragma unroll
        for (int nt = 0; nt < 4; nt++) {
            u[nt][0] = fmaxf(d[nt][0] + bb0[nt], 0.f);
            u[nt][1] = fmaxf(d[nt][1] + bb1[nt], 0.f);
            u[nt][2] = fmaxf(d[nt][2] + bb0[nt], 0.f);
            u[nt][3] = fmaxf(d[nt][3] + bb1[nt], 0.f);
        }

        if (!LAST) {
            uint32_t ua[2][4];
#pragma unroll
            for (int kt2 = 0; kt2 < 2; kt2++) {
                int s = kt2 * 2;
                ua[kt2][0] = packh2(u[s][0], u[s][1]);
                ua[kt2][1] = packh2(u[s][2], u[s][3]);
                ua[kt2][2] = packh2(u[s + 1][0], u[s + 1][1]);
                ua[kt2][3] = packh2(u[s + 1][2], u[s + 1][3]);
            }
            float e[4][4];
#pragma unroll
            for (int nt = 0; nt < 4; nt++) { e[nt][0] = e[nt][1] = e[nt][2] = e[nt][3] = 0.f; }
#pragma unroll
            for (int kt2 = 0; kt2 < 2; kt2++)
#pragma unroll
                for (int nt = 0; nt < 4; nt++) {
                    mma16816(e[nt][0], e[nt][1], e[nt][2], e[nt][3],
                             ua[kt2][0], ua[kt2][1], ua[kt2][2], ua[kt2][3],
                             bah[kt2][nt][0], bah[kt2][nt][1]);
                    mma16816(e[nt][0], e[nt][1], e[nt][2], e[nt][3],
                             ua[kt2][0], ua[kt2][1], ua[kt2][2], ua[kt2][3],
                             bal[kt2][nt][0], bal[kt2][nt][1]);
                }
#pragma unroll
            for (int nt = 0; nt < 4; nt++) {
                po[(base + row) * 16 + nt * 4 + (lane & 3)] = packh2(e[nt][0], e[nt][1]);
                po[(base + row + 8) * 16 + nt * 4 + (lane & 3)] = packh2(e[nt][2], e[nt][3]);
            }
        } else {
            float m0 = (base + row < n_nodes) ? 1.0f : 0.0f;
            float m1 = (base + row + 8 < n_nodes) ? 1.0f : 0.0f;
#pragma unroll
            for (int nt = 0; nt < 4; nt++) {
                pacc0[nt] += m0 * u[nt][0] + m1 * u[nt][2];
                pacc1[nt] += m0 * u[nt][1] + m1 * u[nt][3];
            }
        }
    }

    if (LAST) {
#pragma unroll
        for (int nt = 0; nt < 4; nt++) {
            atomicAdd(&ps[nt * 8 + kq], pacc0[nt]);
            atomicAdd(&ps[nt * 8 + kq + 1], pacc1[nt]);
        }
        __syncthreads();
        if (threadIdx.x < DIM) atomicAdd(&g_pool[threadIdx.x], ps[threadIdx.x]);
    }
}

// ---------------- head: consumes g_pool, then RESETS it for next call --------
__global__ void k_head(const float* __restrict__ fcw, const float* __restrict__ fcb,
                       const float* __restrict__ outw, const float* __restrict__ outb,
                       float* __restrict__ out) {
    __shared__ float g2[DIM];
    __shared__ float gp[DIM];
    int j = threadIdx.x;
    float pv = g_pool[j];
    g_pool[j] = 0.0f;
    gp[j] = pv;
    __syncwarp();
    float acc = fcb[j];
    for (int k = 0; k < DIM; k++) acc = fmaf(gp[k], fcw[k * DIM + j], acc);
    g2[j] = fmaxf(acc, 0.0f);
    __syncwarp();
    float o = outb[j];
    for (int k = 0; k < DIM; k++) o = fmaf(g2[k], outw[k * DIM + j], o);
    out[j] = o;
}

// ---------------- launch ------------------------------------------------------
extern "C" void kernel_launch(void* const* d_in, const int* in_sizes, int n_in,
                              void* d_out, int out_size) {
    const float* x    = (const float*)d_in[0];
    const int*   ei   = (const int*)d_in[1];
    const float* w1a  = (const float*)d_in[2];
    const float* b1a  = (const float*)d_in[3];
    const float* w1b  = (const float*)d_in[4];
    const float* b1b  = (const float*)d_in[5];
    const float* wa   = (const float*)d_in[6];
    const float* ba   = (const float*)d_in[7];
    const float* wb   = (const float*)d_in[8];
    const float* bb   = (const float*)d_in[9];
    const float* fcw  = (const float*)d_in[10];
    const float* fcb  = (const float*)d_in[11];
    const float* outw = (const float*)d_in[12];
    const float* outb = (const float*)d_in[13];

    int in_dim  = in_sizes[2] / DIM;
    int n_nodes = in_sizes[0] / in_dim;
    int n_edges = in_sizes[1] / 2;
    const int* src = ei;
    const int* dst = ei + n_edges;

    __half *p0, *p1;
    cudaGetSymbolAddress((void**)&p0, g_p0);
    cudaGetSymbolAddress((void**)&p1, g_p1);

    // CSR build
    k_hist<<<1024, 256>>>(dst, n_edges);
    int nb = (n_nodes + SCAN_BLK - 1) / SCAN_BLK;
    k_scan1<<<nb, SCAN_BLK>>>(n_nodes);
    k_scan3<<<256, 256>>>(n_nodes, n_edges, nb);
    k_fill<<<2048, 256>>>(src, dst, n_edges);

    // tensor-core projection (standalone: its 152 regs no longer throttle fill)
    k_proj<<<512, 256>>>(x, w1a, n_nodes, in_dim);

    // 5 layers: agg (gather) + mlp (tensor-core GEMM chain)
    k_agg<<<2048, 256>>>(p0, b1a, n_nodes);
    k_mlp<false><<<256, 256>>>(p1, w1b, b1b, wa + 0 * DIM * DIM, n_nodes);

    k_agg<<<2048, 256>>>(p1, ba + 0 * DIM, n_nodes);
    k_mlp<false><<<256, 256>>>(p0, wb + 0 * DIM * DIM, bb + 0 * DIM,
                               wa + 1 * DIM * DIM, n_nodes);

    k_agg<<<2048, 256>>>(p0, ba + 1 * DIM, n_nodes);
    k_mlp<false><<<256, 256>>>(p1, wb + 1 * DIM * DIM, bb + 1 * DIM,
                               wa + 2 * DIM * DIM, n_nodes);

    k_agg<<<2048, 256>>>(p1, ba + 2 * DIM, n_nodes);
    k_mlp<false><<<256, 256>>>(p0, wb + 2 * DIM * DIM, bb + 2 * DIM,
                               wa + 3 * DIM * DIM, n_nodes);

    k_agg<<<2048, 256>>>(p0, ba + 3 * DIM, n_nodes);
    k_mlp<true><<<256, 256>>>(p1, wb + 3 * DIM * DIM, bb + 3 * DIM,
                              nullptr, n_nodes);

    // graph head (also resets g_pool)
    k_head<<<1, 32>>>(fcw, fcb, outw, outb, (float*)d_out);
}